// round 4
// baseline (speedup 1.0000x reference)
#include <cuda_runtime.h>

#define NN 50000
#define NE_MAX 700000
#define DD 128

// scratch (static __device__ — zero-initialized at module load)
__device__ int   g_cnt[NN];                            // in-degree histogram (re-zeroed by k_scatter each replay)
__device__ int   g_off[NN + 1];                        // CSR offsets
__device__ int   g_cur[NN];                            // scatter cursors
__device__ float g_dinv[NN];                           // 1/sqrt(deg+1)
__device__ int   g_src_sorted[NE_MAX];                 // edge srcs sorted by dst
__device__ __align__(16) float g_y[(size_t)NN * DD];   // y = A_hat @ x

// ---------------- histogram ----------------
__global__ void k_hist(const int* __restrict__ dst, int e) {
    int i = blockIdx.x * blockDim.x + threadIdx.x;
    if (i < e) {
        unsigned d = (unsigned)dst[i];
        if (d < NN) atomicAdd(&g_cnt[d], 1);
    }
}

// ---------------- fused scan: offsets + cursors + dinv, single block ----------------
__global__ void __launch_bounds__(1024) k_scan_all(int n) {
    __shared__ int ssum[1024];
    int tid = threadIdx.x;
    int ch = (n + 1023) >> 10;          // chunk size per thread
    int beg = tid * ch;
    int end = min(beg + ch, n);

    int s = 0;
    for (int i = beg; i < end; i++) s += g_cnt[i];
    ssum[tid] = s;
    __syncthreads();
    for (int ofs = 1; ofs < 1024; ofs <<= 1) {
        int t = (tid >= ofs) ? ssum[tid - ofs] : 0;
        __syncthreads();
        ssum[tid] += t;
        __syncthreads();
    }
    int run = (tid == 0) ? 0 : ssum[tid - 1];
    for (int i = beg; i < end; i++) {
        int c = g_cnt[i];
        g_off[i] = run;
        g_cur[i] = run;
        g_dinv[i] = rsqrtf((float)c + 1.0f);   // +1 self loop
        run += c;
    }
    if (tid == 1023) g_off[n] = ssum[1023];
}

// ---------------- scatter edges into dst-sorted order (+ re-zero g_cnt) ----------------
__global__ void k_scatter(const int* __restrict__ src, const int* __restrict__ dst, int e) {
    int i = blockIdx.x * blockDim.x + threadIdx.x;
    if (i < NN) g_cnt[i] = 0;   // re-arm histogram for the next graph replay
    if (i < e) {
        unsigned s = (unsigned)src[i], d = (unsigned)dst[i];
        if (s < NN && d < NN) {
            int p = atomicAdd(&g_cur[d], 1);
            if (p < NE_MAX) g_src_sorted[p] = (int)s;
        }
    }
}

// ---------------- CSR gather-aggregate: y[d] = self + sum, no atomics ----------------
// one warp per dst node, one float4 per lane, unroll-4 over edges for MLP
__global__ void __launch_bounds__(256) k_agg_gather(const float* __restrict__ x, int n) {
    int warp = (blockIdx.x * blockDim.x + threadIdx.x) >> 5;
    int lane = threadIdx.x & 31;
    if (warp >= n) return;
    int d = warp;

    float dd = g_dinv[d];
    float4 acc = __ldg((const float4*)x + (size_t)d * 32 + lane);
    float ss = dd * dd;
    acc.x *= ss; acc.y *= ss; acc.z *= ss; acc.w *= ss;

    int beg = g_off[d], end = g_off[d + 1];
    int j = beg;
    for (; j + 4 <= end; j += 4) {
        int s0 = __ldg(g_src_sorted + j);
        int s1 = __ldg(g_src_sorted + j + 1);
        int s2 = __ldg(g_src_sorted + j + 2);
        int s3 = __ldg(g_src_sorted + j + 3);
        float n0 = g_dinv[s0] * dd;
        float n1 = g_dinv[s1] * dd;
        float n2 = g_dinv[s2] * dd;
        float n3 = g_dinv[s3] * dd;
        float4 v0 = __ldg((const float4*)x + (size_t)s0 * 32 + lane);
        float4 v1 = __ldg((const float4*)x + (size_t)s1 * 32 + lane);
        float4 v2 = __ldg((const float4*)x + (size_t)s2 * 32 + lane);
        float4 v3 = __ldg((const float4*)x + (size_t)s3 * 32 + lane);
        acc.x += v0.x * n0 + v1.x * n1 + v2.x * n2 + v3.x * n3;
        acc.y += v0.y * n0 + v1.y * n1 + v2.y * n2 + v3.y * n3;
        acc.z += v0.z * n0 + v1.z * n1 + v2.z * n2 + v3.z * n3;
        acc.w += v0.w * n0 + v1.w * n1 + v2.w * n2 + v3.w * n3;
    }
    for (; j < end; j++) {
        int s0 = __ldg(g_src_sorted + j);
        float n0 = g_dinv[s0] * dd;
        float4 v0 = __ldg((const float4*)x + (size_t)s0 * 32 + lane);
        acc.x += v0.x * n0; acc.y += v0.y * n0;
        acc.z += v0.z * n0; acc.w += v0.w * n0;
    }
    ((float4*)g_y)[(size_t)d * 32 + lane] = acc;
}

// ---------------- fused dual GEMM + bias + relu + mean ----------------
// out = 0.5*(relu(y@W1+b1) + relu(y@W2+b2)); BM=128 nodes/block, 512 threads
__device__ __forceinline__ void ffma2(unsigned long long& d,
                                      unsigned long long a,
                                      unsigned long long b) {
    asm volatile("fma.rn.f32x2 %0, %1, %2, %0;" : "+l"(d) : "l"(a), "l"(b));
}

#define BM 128

extern "C" __global__ void __launch_bounds__(512, 1)
k_gemm_fused(const float* __restrict__ W1, const float* __restrict__ b1,
             const float* __restrict__ W2, const float* __restrict__ b2,
             float* __restrict__ out, int n) {
    extern __shared__ float smem[];
    float* W1s = smem;                 // 128*128
    float* W2s = smem + 16384;         // 128*128
    float* Ys  = smem + 32768;         // BM*128

    int tid = threadIdx.x;
    int m0 = blockIdx.x * BM;

    for (int i = tid; i < 4096; i += 512) {
        ((float4*)W1s)[i] = ((const float4*)W1)[i];
        ((float4*)W2s)[i] = ((const float4*)W2)[i];
    }
    for (int i = tid; i < BM * 32; i += 512) {
        int row = i >> 5;
        int g = m0 + row;
        float4 v;
        if (g < n) v = ((const float4*)g_y)[(size_t)g * 32 + (i & 31)];
        else       v = make_float4(0.f, 0.f, 0.f, 0.f);
        ((float4*)Ys)[i] = v;
    }
    __syncthreads();

    int cg = tid & 15;        // 16 col-groups of 8 cols
    int ng = tid >> 4;        // 32 node-groups of 4 nodes
    int col0 = cg * 8;
    int row0 = ng * 4;

    unsigned long long acc1[4][4];
    unsigned long long acc2[4][4];
    #pragma unroll
    for (int i = 0; i < 4; i++)
        #pragma unroll
        for (int j = 0; j < 4; j++) { acc1[i][j] = 0ull; acc2[i][j] = 0ull; }

    #pragma unroll 4
    for (int k = 0; k < 128; k++) {
        ulonglong2 w1a = *reinterpret_cast<const ulonglong2*>(&W1s[k * 128 + col0]);
        ulonglong2 w1b = *reinterpret_cast<const ulonglong2*>(&W1s[k * 128 + col0 + 4]);
        ulonglong2 w2a = *reinterpret_cast<const ulonglong2*>(&W2s[k * 128 + col0]);
        ulonglong2 w2b = *reinterpret_cast<const ulonglong2*>(&W2s[k * 128 + col0 + 4]);
        #pragma unroll
        for (int i = 0; i < 4; i++) {
            float yv = Ys[(row0 + i) * 128 + k];
            unsigned long long yy;
            asm("mov.b64 %0, {%1, %1};" : "=l"(yy) : "r"(__float_as_uint(yv)));
            ffma2(acc1[i][0], yy, w1a.x);
            ffma2(acc1[i][1], yy, w1a.y);
            ffma2(acc1[i][2], yy, w1b.x);
            ffma2(acc1[i][3], yy, w1b.y);
            ffma2(acc2[i][0], yy, w2a.x);
            ffma2(acc2[i][1], yy, w2a.y);
            ffma2(acc2[i][2], yy, w2b.x);
            ffma2(acc2[i][3], yy, w2b.y);
        }
    }

    #pragma unroll
    for (int i = 0; i < 4; i++) {
        int g = m0 + row0 + i;
        if (g >= n) continue;
        float* o = out + (size_t)g * 128 + col0;
        #pragma unroll
        for (int j = 0; j < 4; j++) {
            float a1x, a1y, a2x, a2y;
            asm("mov.b64 {%0, %1}, %2;" : "=f"(a1x), "=f"(a1y) : "l"(acc1[i][j]));
            asm("mov.b64 {%0, %1}, %2;" : "=f"(a2x), "=f"(a2y) : "l"(acc2[i][j]));
            int c = col0 + j * 2;
            float r1x = fmaxf(a1x + b1[c],     0.f);
            float r1y = fmaxf(a1y + b1[c + 1], 0.f);
            float r2x = fmaxf(a2x + b2[c],     0.f);
            float r2y = fmaxf(a2y + b2[c + 1], 0.f);
            o[j * 2]     = 0.5f * (r1x + r2x);
            o[j * 2 + 1] = 0.5f * (r1y + r2y);
        }
    }
}

extern "C" void kernel_launch(void* const* d_in, const int* in_sizes, int n_in,
                              void* d_out, int out_size) {
    const float* x  = (const float*)d_in[0];
    const int*   ei = (const int*)d_in[1];
    const float* W1 = (const float*)d_in[2];
    const float* b1 = (const float*)d_in[3];
    const float* W2 = (const float*)d_in[4];
    const float* b2 = (const float*)d_in[5];
    float* out = (float*)d_out;

    int n_nodes = in_sizes[0] / DD;       // 50000
    int n_edges = in_sizes[1] / 2;        // 600000
    const int* src = ei;
    const int* dst = ei + n_edges;

    int nb_edges = (n_edges + 255) / 256;

    // 1: histogram   2: fused scan   3: scatter(+rezero)   4: gather   5: gemm
    k_hist<<<nb_edges, 256>>>(dst, n_edges);
    k_scan_all<<<1, 1024>>>(n_nodes);
    k_scatter<<<nb_edges, 256>>>(src, dst, n_edges);
    {
        int blocks = (n_nodes * 32 + 255) / 256;
        k_agg_gather<<<blocks, 256>>>(x, n_nodes);
    }
    {
        int smem_bytes = (16384 * 2 + BM * 128) * 4;   // 196608
        cudaFuncSetAttribute(k_gemm_fused,
                             cudaFuncAttributeMaxDynamicSharedMemorySize, smem_bytes);
        int gblocks = (n_nodes + BM - 1) / BM;
        k_gemm_fused<<<gblocks, 512, smem_bytes>>>(W1, b1, W2, b2, out, n_nodes);
    }
}

// round 5
// speedup vs baseline: 1.4432x; 1.4432x over previous
#include <cuda_runtime.h>

#define NN 50000
#define NE_MAX 700000
#define DD 128

// scratch (static __device__ — zero-initialized at module load)
__device__ int   g_cnt[NN];                            // in-degree histogram (re-zeroed by k_scatter)
__device__ int   g_off[NN + 1];                        // CSR offsets
__device__ int   g_cur[NN];                            // scatter cursors
__device__ int   g_bsums[64];                          // block sums for scan
__device__ float g_dinv[NN];                           // 1/sqrt(deg+1)
__device__ int   g_src_sorted[NE_MAX];                 // edge srcs sorted by dst
__device__ __align__(16) float g_y[(size_t)NN * DD];   // y = A_hat @ x

// ---------------- histogram ----------------
__global__ void k_hist(const int* __restrict__ dst, int e) {
    int i = blockIdx.x * blockDim.x + threadIdx.x;
    if (i < e) {
        unsigned d = (unsigned)dst[i];
        if (d < NN) atomicAdd(&g_cnt[d], 1);
    }
}

// ---------------- exclusive scan (3 coalesced phases) ----------------
__global__ void __launch_bounds__(1024) k_scan1(int n) {
    __shared__ int sm[1024];
    int tid = threadIdx.x;
    int gid = blockIdx.x * 1024 + tid;
    int v = (gid < n) ? g_cnt[gid] : 0;
    sm[tid] = v;
    __syncthreads();
    for (int ofs = 1; ofs < 1024; ofs <<= 1) {
        int t = (tid >= ofs) ? sm[tid - ofs] : 0;
        __syncthreads();
        sm[tid] += t;
        __syncthreads();
    }
    if (gid < n) g_off[gid] = sm[tid] - v;   // block-local exclusive
    if (tid == 1023) g_bsums[blockIdx.x] = sm[1023];
}

__global__ void k_scan2(int nblocks, int n) {
    if (threadIdx.x == 0 && blockIdx.x == 0) {
        int run = 0;
        for (int i = 0; i < nblocks; i++) {
            int v = g_bsums[i];
            g_bsums[i] = run;
            run += v;
        }
        g_off[n] = run;   // total valid edges
    }
}

__global__ void k_scan3(int n) {
    int i = blockIdx.x * blockDim.x + threadIdx.x;
    if (i < n) {
        int o = g_off[i] + g_bsums[i >> 10];
        g_off[i] = o;
        g_cur[i] = o;
        g_dinv[i] = rsqrtf((float)g_cnt[i] + 1.0f);   // +1 self loop
    }
}

// ---------------- scatter edges into dst-sorted order (+ re-zero g_cnt) ----------------
__global__ void k_scatter(const int* __restrict__ src, const int* __restrict__ dst, int e) {
    int i = blockIdx.x * blockDim.x + threadIdx.x;
    if (i < NN) g_cnt[i] = 0;   // re-arm histogram for next graph replay (cnt no longer needed)
    if (i < e) {
        unsigned s = (unsigned)src[i], d = (unsigned)dst[i];
        if (s < NN && d < NN) {
            int p = atomicAdd(&g_cur[d], 1);
            if (p < NE_MAX) g_src_sorted[p] = (int)s;
        }
    }
}

// ---------------- CSR gather-aggregate: y[d] = self + sum, no atomics ----------------
// one warp per dst node, one float4 per lane, unroll-4 over edges for MLP
__global__ void __launch_bounds__(256) k_agg_gather(const float* __restrict__ x, int n) {
    int warp = (blockIdx.x * blockDim.x + threadIdx.x) >> 5;
    int lane = threadIdx.x & 31;
    if (warp >= n) return;
    int d = warp;

    float dd = g_dinv[d];
    float4 acc = __ldg((const float4*)x + (size_t)d * 32 + lane);
    float ss = dd * dd;
    acc.x *= ss; acc.y *= ss; acc.z *= ss; acc.w *= ss;

    int beg = g_off[d], end = g_off[d + 1];
    int j = beg;
    for (; j + 4 <= end; j += 4) {
        int s0 = __ldg(g_src_sorted + j);
        int s1 = __ldg(g_src_sorted + j + 1);
        int s2 = __ldg(g_src_sorted + j + 2);
        int s3 = __ldg(g_src_sorted + j + 3);
        float n0 = g_dinv[s0] * dd;
        float n1 = g_dinv[s1] * dd;
        float n2 = g_dinv[s2] * dd;
        float n3 = g_dinv[s3] * dd;
        float4 v0 = __ldg((const float4*)x + (size_t)s0 * 32 + lane);
        float4 v1 = __ldg((const float4*)x + (size_t)s1 * 32 + lane);
        float4 v2 = __ldg((const float4*)x + (size_t)s2 * 32 + lane);
        float4 v3 = __ldg((const float4*)x + (size_t)s3 * 32 + lane);
        acc.x += v0.x * n0 + v1.x * n1 + v2.x * n2 + v3.x * n3;
        acc.y += v0.y * n0 + v1.y * n1 + v2.y * n2 + v3.y * n3;
        acc.z += v0.z * n0 + v1.z * n1 + v2.z * n2 + v3.z * n3;
        acc.w += v0.w * n0 + v1.w * n1 + v2.w * n2 + v3.w * n3;
    }
    for (; j < end; j++) {
        int s0 = __ldg(g_src_sorted + j);
        float n0 = g_dinv[s0] * dd;
        float4 v0 = __ldg((const float4*)x + (size_t)s0 * 32 + lane);
        acc.x += v0.x * n0; acc.y += v0.y * n0;
        acc.z += v0.z * n0; acc.w += v0.w * n0;
    }
    ((float4*)g_y)[(size_t)d * 32 + lane] = acc;
}

// ---------------- fused dual GEMM + bias + relu + mean ----------------
// out = 0.5*(relu(y@W1+b1) + relu(y@W2+b2)); BM=128 nodes/block, 512 threads
__device__ __forceinline__ void ffma2(unsigned long long& d,
                                      unsigned long long a,
                                      unsigned long long b) {
    asm volatile("fma.rn.f32x2 %0, %1, %2, %0;" : "+l"(d) : "l"(a), "l"(b));
}

#define BM 128

extern "C" __global__ void __launch_bounds__(512, 1)
k_gemm_fused(const float* __restrict__ W1, const float* __restrict__ b1,
             const float* __restrict__ W2, const float* __restrict__ b2,
             float* __restrict__ out, int n) {
    extern __shared__ float smem[];
    float* W1s = smem;                 // 128*128
    float* W2s = smem + 16384;         // 128*128
    float* Ys  = smem + 32768;         // BM*128

    int tid = threadIdx.x;
    int m0 = blockIdx.x * BM;

    for (int i = tid; i < 4096; i += 512) {
        ((float4*)W1s)[i] = ((const float4*)W1)[i];
        ((float4*)W2s)[i] = ((const float4*)W2)[i];
    }
    for (int i = tid; i < BM * 32; i += 512) {
        int row = i >> 5;
        int g = m0 + row;
        float4 v;
        if (g < n) v = ((const float4*)g_y)[(size_t)g * 32 + (i & 31)];
        else       v = make_float4(0.f, 0.f, 0.f, 0.f);
        ((float4*)Ys)[i] = v;
    }
    __syncthreads();

    int cg = tid & 15;        // 16 col-groups of 8 cols
    int ng = tid >> 4;        // 32 node-groups of 4 nodes
    int col0 = cg * 8;
    int row0 = ng * 4;

    unsigned long long acc1[4][4];
    unsigned long long acc2[4][4];
    #pragma unroll
    for (int i = 0; i < 4; i++)
        #pragma unroll
        for (int j = 0; j < 4; j++) { acc1[i][j] = 0ull; acc2[i][j] = 0ull; }

    #pragma unroll 4
    for (int k = 0; k < 128; k++) {
        ulonglong2 w1a = *reinterpret_cast<const ulonglong2*>(&W1s[k * 128 + col0]);
        ulonglong2 w1b = *reinterpret_cast<const ulonglong2*>(&W1s[k * 128 + col0 + 4]);
        ulonglong2 w2a = *reinterpret_cast<const ulonglong2*>(&W2s[k * 128 + col0]);
        ulonglong2 w2b = *reinterpret_cast<const ulonglong2*>(&W2s[k * 128 + col0 + 4]);
        #pragma unroll
        for (int i = 0; i < 4; i++) {
            float yv = Ys[(row0 + i) * 128 + k];
            unsigned long long yy;
            asm("mov.b64 %0, {%1, %1};" : "=l"(yy) : "r"(__float_as_uint(yv)));
            ffma2(acc1[i][0], yy, w1a.x);
            ffma2(acc1[i][1], yy, w1a.y);
            ffma2(acc1[i][2], yy, w1b.x);
            ffma2(acc1[i][3], yy, w1b.y);
            ffma2(acc2[i][0], yy, w2a.x);
            ffma2(acc2[i][1], yy, w2a.y);
            ffma2(acc2[i][2], yy, w2b.x);
            ffma2(acc2[i][3], yy, w2b.y);
        }
    }

    #pragma unroll
    for (int i = 0; i < 4; i++) {
        int g = m0 + row0 + i;
        if (g >= n) continue;
        float* o = out + (size_t)g * 128 + col0;
        #pragma unroll
        for (int j = 0; j < 4; j++) {
            float a1x, a1y, a2x, a2y;
            asm("mov.b64 {%0, %1}, %2;" : "=f"(a1x), "=f"(a1y) : "l"(acc1[i][j]));
            asm("mov.b64 {%0, %1}, %2;" : "=f"(a2x), "=f"(a2y) : "l"(acc2[i][j]));
            int c = col0 + j * 2;
            float r1x = fmaxf(a1x + b1[c],     0.f);
            float r1y = fmaxf(a1y + b1[c + 1], 0.f);
            float r2x = fmaxf(a2x + b2[c],     0.f);
            float r2y = fmaxf(a2y + b2[c + 1], 0.f);
            o[j * 2]     = 0.5f * (r1x + r2x);
            o[j * 2 + 1] = 0.5f * (r1y + r2y);
        }
    }
}

extern "C" void kernel_launch(void* const* d_in, const int* in_sizes, int n_in,
                              void* d_out, int out_size) {
    const float* x  = (const float*)d_in[0];
    const int*   ei = (const int*)d_in[1];
    const float* W1 = (const float*)d_in[2];
    const float* b1 = (const float*)d_in[3];
    const float* W2 = (const float*)d_in[4];
    const float* b2 = (const float*)d_in[5];
    float* out = (float*)d_out;

    int n_nodes = in_sizes[0] / DD;       // 50000
    int n_edges = in_sizes[1] / 2;        // 600000
    const int* src = ei;
    const int* dst = ei + n_edges;

    int nb_nodes = (n_nodes + 255) / 256;
    int nb_edges = (n_edges + 255) / 256;
    int nscan = (n_nodes + 1023) / 1024;

    k_hist<<<nb_edges, 256>>>(dst, n_edges);
    k_scan1<<<nscan, 1024>>>(n_nodes);
    k_scan2<<<1, 32>>>(nscan, n_nodes);
    k_scan3<<<nb_nodes, 256>>>(n_nodes);
    k_scatter<<<nb_edges, 256>>>(src, dst, n_edges);
    {
        int blocks = (n_nodes * 32 + 255) / 256;
        k_agg_gather<<<blocks, 256>>>(x, n_nodes);
    }
    {
        int smem_bytes = (16384 * 2 + BM * 128) * 4;   // 196608
        cudaFuncSetAttribute(k_gemm_fused,
                             cudaFuncAttributeMaxDynamicSharedMemorySize, smem_bytes);
        int gblocks = (n_nodes + BM - 1) / BM;
        k_gemm_fused<<<gblocks, 512, smem_bytes>>>(W1, b1, W2, b2, out, n_nodes);
    }
}

// round 6
// speedup vs baseline: 2.9619x; 2.0523x over previous
#include <cuda_runtime.h>

#define NN 50000
#define NE_MAX 700000
#define DD 128

// scratch (static __device__ — zero-initialized at module load)
__device__ int   g_cnt[NN];                 // in-degree histogram (re-zeroed by k_scatter)
__device__ int   g_off[NN + 1];             // CSR offsets
__device__ int   g_cur[NN];                 // scatter cursors
__device__ int   g_bsums[64];               // block sums for scan
__device__ float g_dinv[NN];                // 1/sqrt(deg+1)
__device__ int   g_src_sorted[NE_MAX];      // edge srcs sorted by dst

// ---------------- histogram ----------------
__global__ void k_hist(const int* __restrict__ dst, int e) {
    int i = blockIdx.x * blockDim.x + threadIdx.x;
    if (i < e) {
        unsigned d = (unsigned)dst[i];
        if (d < NN) atomicAdd(&g_cnt[d], 1);
    }
}

// ---------------- scan phase 1: per-block inclusive scan (coalesced) ----------------
__global__ void __launch_bounds__(1024) k_scan1(int n) {
    __shared__ int sm[1024];
    int tid = threadIdx.x;
    int gid = blockIdx.x * 1024 + tid;
    int v = (gid < n) ? g_cnt[gid] : 0;
    sm[tid] = v;
    __syncthreads();
    for (int ofs = 1; ofs < 1024; ofs <<= 1) {
        int t = (tid >= ofs) ? sm[tid - ofs] : 0;
        __syncthreads();
        sm[tid] += t;
        __syncthreads();
    }
    if (gid < n) g_off[gid] = sm[tid] - v;   // block-local exclusive
    if (tid == 1023) g_bsums[blockIdx.x] = sm[1023];
}

// ---------------- scan phase 2+3 fused: apply block offsets + cursors + dinv ------
__global__ void k_scan23(int nblocks, int n) {
    __shared__ int pre[65];
    int tid = threadIdx.x;
    if (tid == 0) {
        int run = 0;
        for (int i = 0; i < nblocks; i++) { int v = g_bsums[i]; pre[i] = run; run += v; }
        pre[nblocks] = run;
    }
    __syncthreads();
    int i = blockIdx.x * blockDim.x + tid;
    if (i < n) {
        int o = g_off[i] + pre[i >> 10];
        g_off[i] = o;
        g_cur[i] = o;
        g_dinv[i] = rsqrtf((float)g_cnt[i] + 1.0f);   // +1 self loop
    }
    if (i == 0) g_off[n] = pre[nblocks];
}

// ---------------- scatter edges into dst-sorted order (+ re-zero g_cnt) ----------
__global__ void k_scatter(const int* __restrict__ src, const int* __restrict__ dst, int e) {
    int i = blockIdx.x * blockDim.x + threadIdx.x;
    if (i < NN) g_cnt[i] = 0;   // re-arm histogram for next graph replay
    if (i < e) {
        unsigned s = (unsigned)src[i], d = (unsigned)dst[i];
        if (s < NN && d < NN) {
            int p = atomicAdd(&g_cur[d], 1);
            if (p < NE_MAX) g_src_sorted[p] = (int)s;
        }
    }
}

// ---------------- mega kernel: CSR gather + dual tf32 MMA GEMM + epilogue --------
// block: 128 nodes, 512 threads (16 warps = 4m x 4n), smem pitch 132 (bank-safe)

#define BM   128
#define PITCH 132

__device__ __forceinline__ float tf32r(float f) {
    unsigned u;
    asm("cvt.rna.tf32.f32 %0, %1;" : "=r"(u) : "f"(f));
    return __uint_as_float(u);
}

__device__ __forceinline__ void mma_tf32(float* c, const unsigned* a,
                                         unsigned b0, unsigned b1) {
    asm volatile(
        "mma.sync.aligned.m16n8k8.row.col.f32.tf32.tf32.f32 "
        "{%0,%1,%2,%3}, {%4,%5,%6,%7}, {%8,%9}, {%0,%1,%2,%3};"
        : "+f"(c[0]), "+f"(c[1]), "+f"(c[2]), "+f"(c[3])
        : "r"(a[0]), "r"(a[1]), "r"(a[2]), "r"(a[3]), "r"(b0), "r"(b1));
}

__global__ void __launch_bounds__(512, 1)
k_mega(const float* __restrict__ x,
       const float* __restrict__ W1, const float* __restrict__ b1,
       const float* __restrict__ W2, const float* __restrict__ b2,
       float* __restrict__ out, int n) {
    extern __shared__ float smem[];
    float* W1s = smem;                       // 128 x PITCH
    float* W2s = smem + 128 * PITCH;         // 128 x PITCH
    float* Ys  = smem + 2 * 128 * PITCH;     // BM x PITCH

    int tid  = threadIdx.x;
    int lane = tid & 31;
    int wid  = tid >> 5;
    int m0   = blockIdx.x * BM;

    // ---- stage weights (tf32-rounded) ----
    for (int i = tid; i < 4096; i += 512) {
        int row = i >> 5, c4 = (i & 31) << 2;
        float4 v1 = ((const float4*)W1)[i];
        float4 v2 = ((const float4*)W2)[i];
        *(float4*)&W1s[row * PITCH + c4] =
            make_float4(tf32r(v1.x), tf32r(v1.y), tf32r(v1.z), tf32r(v1.w));
        *(float4*)&W2s[row * PITCH + c4] =
            make_float4(tf32r(v2.x), tf32r(v2.y), tf32r(v2.z), tf32r(v2.w));
    }

    // ---- CSR gather of this block's 128 rows into Ys (tf32-rounded) ----
    // warp w handles rows w*8 .. w*8+7; one float4 per lane
    for (int i = 0; i < 8; i++) {
        int row = wid * 8 + i;
        int d = m0 + row;
        float4 acc = make_float4(0.f, 0.f, 0.f, 0.f);
        if (d < n) {
            float dd = g_dinv[d];
            acc = __ldg((const float4*)x + (size_t)d * 32 + lane);
            float ss = dd * dd;
            acc.x *= ss; acc.y *= ss; acc.z *= ss; acc.w *= ss;
            int beg = g_off[d], end = g_off[d + 1];
            int j = beg;
            for (; j + 4 <= end; j += 4) {
                int s0 = __ldg(g_src_sorted + j);
                int s1 = __ldg(g_src_sorted + j + 1);
                int s2 = __ldg(g_src_sorted + j + 2);
                int s3 = __ldg(g_src_sorted + j + 3);
                float n0 = g_dinv[s0] * dd;
                float n1 = g_dinv[s1] * dd;
                float n2 = g_dinv[s2] * dd;
                float n3 = g_dinv[s3] * dd;
                float4 v0 = __ldg((const float4*)x + (size_t)s0 * 32 + lane);
                float4 v1 = __ldg((const float4*)x + (size_t)s1 * 32 + lane);
                float4 v2 = __ldg((const float4*)x + (size_t)s2 * 32 + lane);
                float4 v3 = __ldg((const float4*)x + (size_t)s3 * 32 + lane);
                acc.x += v0.x * n0 + v1.x * n1 + v2.x * n2 + v3.x * n3;
                acc.y += v0.y * n0 + v1.y * n1 + v2.y * n2 + v3.y * n3;
                acc.z += v0.z * n0 + v1.z * n1 + v2.z * n2 + v3.z * n3;
                acc.w += v0.w * n0 + v1.w * n1 + v2.w * n2 + v3.w * n3;
            }
            for (; j < end; j++) {
                int s0 = __ldg(g_src_sorted + j);
                float n0 = g_dinv[s0] * dd;
                float4 v0 = __ldg((const float4*)x + (size_t)s0 * 32 + lane);
                acc.x += v0.x * n0; acc.y += v0.y * n0;
                acc.z += v0.z * n0; acc.w += v0.w * n0;
            }
        }
        *(float4*)&Ys[row * PITCH + lane * 4] =
            make_float4(tf32r(acc.x), tf32r(acc.y), tf32r(acc.z), tf32r(acc.w));
    }
    __syncthreads();

    // ---- dual tf32 MMA: 16 warps = (4m x 4n); warp: 32 rows x (32 W1-cols + 32 W2-cols)
    int wm = wid >> 2, wn = wid & 3;
    int g  = lane >> 2, tig = lane & 3;

    float acc1[2][4][4];
    float acc2[2][4][4];
    #pragma unroll
    for (int mt = 0; mt < 2; mt++)
        #pragma unroll
        for (int nt = 0; nt < 4; nt++)
            #pragma unroll
            for (int q = 0; q < 4; q++) { acc1[mt][nt][q] = 0.f; acc2[mt][nt][q] = 0.f; }

    #pragma unroll 4
    for (int ks = 0; ks < 16; ks++) {
        int k0 = ks * 8;
        unsigned a[2][4];
        #pragma unroll
        for (int mt = 0; mt < 2; mt++) {
            int r = wm * 32 + mt * 16 + g;
            a[mt][0] = __float_as_uint(Ys[r * PITCH + k0 + tig]);
            a[mt][1] = __float_as_uint(Ys[(r + 8) * PITCH + k0 + tig]);
            a[mt][2] = __float_as_uint(Ys[r * PITCH + k0 + tig + 4]);
            a[mt][3] = __float_as_uint(Ys[(r + 8) * PITCH + k0 + tig + 4]);
        }
        #pragma unroll
        for (int nt = 0; nt < 4; nt++) {
            int nc = wn * 32 + nt * 8 + g;
            unsigned w1b0 = __float_as_uint(W1s[(k0 + tig) * PITCH + nc]);
            unsigned w1b1 = __float_as_uint(W1s[(k0 + tig + 4) * PITCH + nc]);
            unsigned w2b0 = __float_as_uint(W2s[(k0 + tig) * PITCH + nc]);
            unsigned w2b1 = __float_as_uint(W2s[(k0 + tig + 4) * PITCH + nc]);
            mma_tf32(acc1[0][nt], a[0], w1b0, w1b1);
            mma_tf32(acc1[1][nt], a[1], w1b0, w1b1);
            mma_tf32(acc2[0][nt], a[0], w2b0, w2b1);
            mma_tf32(acc2[1][nt], a[1], w2b0, w2b1);
        }
    }

    // ---- epilogue: bias + relu + mean, straight to gmem ----
    #pragma unroll
    for (int mt = 0; mt < 2; mt++) {
        int r0 = m0 + wm * 32 + mt * 16 + g;
        #pragma unroll
        for (int nt = 0; nt < 4; nt++) {
            int col = wn * 32 + nt * 8 + 2 * tig;
            float bb1x = __ldg(b1 + col), bb1y = __ldg(b1 + col + 1);
            float bb2x = __ldg(b2 + col), bb2y = __ldg(b2 + col + 1);
            if (r0 < n) {
                float2 o;
                o.x = 0.5f * (fmaxf(acc1[mt][nt][0] + bb1x, 0.f) +
                              fmaxf(acc2[mt][nt][0] + bb2x, 0.f));
                o.y = 0.5f * (fmaxf(acc1[mt][nt][1] + bb1y, 0.f) +
                              fmaxf(acc2[mt][nt][1] + bb2y, 0.f));
                *(float2*)(out + (size_t)r0 * 128 + col) = o;
            }
            if (r0 + 8 < n) {
                float2 o;
                o.x = 0.5f * (fmaxf(acc1[mt][nt][2] + bb1x, 0.f) +
                              fmaxf(acc2[mt][nt][2] + bb2x, 0.f));
                o.y = 0.5f * (fmaxf(acc1[mt][nt][3] + bb1y, 0.f) +
                              fmaxf(acc2[mt][nt][3] + bb2y, 0.f));
                *(float2*)(out + (size_t)(r0 + 8) * 128 + col) = o;
            }
        }
    }
}

extern "C" void kernel_launch(void* const* d_in, const int* in_sizes, int n_in,
                              void* d_out, int out_size) {
    const float* x  = (const float*)d_in[0];
    const int*   ei = (const int*)d_in[1];
    const float* W1 = (const float*)d_in[2];
    const float* b1 = (const float*)d_in[3];
    const float* W2 = (const float*)d_in[4];
    const float* b2 = (const float*)d_in[5];
    float* out = (float*)d_out;

    int n_nodes = in_sizes[0] / DD;       // 50000
    int n_edges = in_sizes[1] / 2;        // 600000
    const int* src = ei;
    const int* dst = ei + n_edges;

    int nb_nodes = (n_nodes + 255) / 256;
    int nb_edges = (n_edges + 255) / 256;
    int nscan = (n_nodes + 1023) / 1024;

    k_hist<<<nb_edges, 256>>>(dst, n_edges);
    k_scan1<<<nscan, 1024>>>(n_nodes);
    k_scan23<<<nb_nodes, 256>>>(nscan, n_nodes);
    k_scatter<<<nb_edges, 256>>>(src, dst, n_edges);
    {
        int smem_bytes = 3 * 128 * PITCH * 4;   // 202752
        cudaFuncSetAttribute(k_mega,
                             cudaFuncAttributeMaxDynamicSharedMemorySize, smem_bytes);
        int gblocks = (n_nodes + BM - 1) / BM;
        k_mega<<<gblocks, 512, smem_bytes>>>(x, W1, b1, W2, b2, out, n_nodes);
    }
}

// round 7
// speedup vs baseline: 3.3034x; 1.1153x over previous
#include <cuda_runtime.h>

#define NN 50000
#define NE_MAX 700000
#define DD 128

// scratch (static __device__ — zero-initialized at module load)
__device__ int   g_cnt[NN];                 // in-degree histogram (re-zeroed by k_scan23)
__device__ int   g_off[NN + 1];             // CSR offsets
__device__ int   g_cur[NN];                 // scatter cursors
__device__ int   g_bsums[64];               // block sums for scan
__device__ float g_dinv[NN];                // 1/sqrt(deg+1)
__device__ int   g_src_sorted[NE_MAX];      // edge srcs sorted by dst

// ---------------- histogram (4 edges/thread for MLP) ----------------
__global__ void k_hist(const int* __restrict__ dst, int e) {
    int i0 = (blockIdx.x * blockDim.x + threadIdx.x) * 4;
    if (i0 + 4 <= e) {
        int4 d4 = *(const int4*)(dst + i0);
        if ((unsigned)d4.x < NN) atomicAdd(&g_cnt[d4.x], 1);
        if ((unsigned)d4.y < NN) atomicAdd(&g_cnt[d4.y], 1);
        if ((unsigned)d4.z < NN) atomicAdd(&g_cnt[d4.z], 1);
        if ((unsigned)d4.w < NN) atomicAdd(&g_cnt[d4.w], 1);
    } else {
        for (int i = i0; i < e; i++) {
            unsigned d = (unsigned)dst[i];
            if (d < NN) atomicAdd(&g_cnt[d], 1);
        }
    }
}

// ---------------- scan phase 1: per-block inclusive scan (coalesced) --------------
__global__ void __launch_bounds__(1024) k_scan1(int n) {
    __shared__ int sm[1024];
    int tid = threadIdx.x;
    int gid = blockIdx.x * 1024 + tid;
    int v = (gid < n) ? g_cnt[gid] : 0;
    sm[tid] = v;
    __syncthreads();
    for (int ofs = 1; ofs < 1024; ofs <<= 1) {
        int t = (tid >= ofs) ? sm[tid - ofs] : 0;
        __syncthreads();
        sm[tid] += t;
        __syncthreads();
    }
    if (gid < n) g_off[gid] = sm[tid] - v;   // block-local exclusive
    if (tid == 1023) g_bsums[blockIdx.x] = sm[1023];
}

// ---------------- scan 2+3 fused: apply block offsets + cursors + dinv + rezero ---
__global__ void k_scan23(int nblocks, int n) {
    __shared__ int pre[65];
    int tid = threadIdx.x;
    if (tid == 0) {
        int run = 0;
        for (int i = 0; i < nblocks; i++) { int v = g_bsums[i]; pre[i] = run; run += v; }
        pre[nblocks] = run;
    }
    __syncthreads();
    int i = blockIdx.x * blockDim.x + tid;
    if (i < n) {
        int o = g_off[i] + pre[i >> 10];
        g_off[i] = o;
        g_cur[i] = o;
        g_dinv[i] = rsqrtf((float)g_cnt[i] + 1.0f);   // +1 self loop
        g_cnt[i] = 0;                                 // re-arm histogram for next replay
    }
    if (i == 0) g_off[n] = pre[nblocks];
}

// ---------------- scatter edges into dst-sorted order (4 edges/thread) -----------
__global__ void k_scatter(const int* __restrict__ src, const int* __restrict__ dst, int e) {
    int i0 = (blockIdx.x * blockDim.x + threadIdx.x) * 4;
    if (i0 + 4 <= e) {
        int4 s4 = *(const int4*)(src + i0);
        int4 d4 = *(const int4*)(dst + i0);
        int p0 = -1, p1 = -1, p2 = -1, p3 = -1;
        if ((unsigned)s4.x < NN && (unsigned)d4.x < NN) p0 = atomicAdd(&g_cur[d4.x], 1);
        if ((unsigned)s4.y < NN && (unsigned)d4.y < NN) p1 = atomicAdd(&g_cur[d4.y], 1);
        if ((unsigned)s4.z < NN && (unsigned)d4.z < NN) p2 = atomicAdd(&g_cur[d4.z], 1);
        if ((unsigned)s4.w < NN && (unsigned)d4.w < NN) p3 = atomicAdd(&g_cur[d4.w], 1);
        if (p0 >= 0 && p0 < NE_MAX) g_src_sorted[p0] = s4.x;
        if (p1 >= 0 && p1 < NE_MAX) g_src_sorted[p1] = s4.y;
        if (p2 >= 0 && p2 < NE_MAX) g_src_sorted[p2] = s4.z;
        if (p3 >= 0 && p3 < NE_MAX) g_src_sorted[p3] = s4.w;
    } else {
        for (int i = i0; i < e; i++) {
            unsigned s = (unsigned)src[i], d = (unsigned)dst[i];
            if (s < NN && d < NN) {
                int p = atomicAdd(&g_cur[d], 1);
                if (p < NE_MAX) g_src_sorted[p] = (int)s;
            }
        }
    }
}

// ---------------- mega kernel: CSR gather + dual tf32 MMA GEMM + epilogue --------
// block: 128 nodes, 512 threads (16 warps = 4m x 4n), smem pitch 132 (bank-safe)

#define BM   128
#define PITCH 132

__device__ __forceinline__ float tf32r(float f) {
    unsigned u;
    asm("cvt.rna.tf32.f32 %0, %1;" : "=r"(u) : "f"(f));
    return __uint_as_float(u);
}

__device__ __forceinline__ void mma_tf32(float* c, const unsigned* a,
                                         unsigned b0, unsigned b1) {
    asm volatile(
        "mma.sync.aligned.m16n8k8.row.col.f32.tf32.tf32.f32 "
        "{%0,%1,%2,%3}, {%4,%5,%6,%7}, {%8,%9}, {%0,%1,%2,%3};"
        : "+f"(c[0]), "+f"(c[1]), "+f"(c[2]), "+f"(c[3])
        : "r"(a[0]), "r"(a[1]), "r"(a[2]), "r"(a[3]), "r"(b0), "r"(b1));
}

__global__ void __launch_bounds__(512, 1)
k_mega(const float* __restrict__ x,
       const float* __restrict__ W1, const float* __restrict__ b1,
       const float* __restrict__ W2, const float* __restrict__ b2,
       float* __restrict__ out, int n) {
    extern __shared__ float smem[];
    float* W1s = smem;                       // 128 x PITCH
    float* W2s = smem + 128 * PITCH;         // 128 x PITCH
    float* Ys  = smem + 2 * 128 * PITCH;     // BM x PITCH
    // per-warp edge scratch: 16 warps x 32 slots of {idx, norm}
    int*   swidx  = (int*)(smem + 3 * 128 * PITCH);
    float* swnorm = (float*)(swidx + 16 * 32);

    int tid  = threadIdx.x;
    int lane = tid & 31;
    int wid  = tid >> 5;
    int m0   = blockIdx.x * BM;

    // ---- stage weights (tf32-rounded) ----
    for (int i = tid; i < 4096; i += 512) {
        int row = i >> 5, c4 = (i & 31) << 2;
        float4 v1 = ((const float4*)W1)[i];
        float4 v2 = ((const float4*)W2)[i];
        *(float4*)&W1s[row * PITCH + c4] =
            make_float4(tf32r(v1.x), tf32r(v1.y), tf32r(v1.z), tf32r(v1.w));
        *(float4*)&W2s[row * PITCH + c4] =
            make_float4(tf32r(v2.x), tf32r(v2.y), tf32r(v2.z), tf32r(v2.w));
    }

    // ---- CSR gather: warp w -> rows w*8..w*8+7; lane-parallel idx/norm prefetch ----
    int* myidx  = swidx + wid * 32;
    float* mynorm = swnorm + wid * 32;

    for (int i = 0; i < 8; i++) {
        int row = wid * 8 + i;
        int d = m0 + row;
        float4 acc = make_float4(0.f, 0.f, 0.f, 0.f);
        if (d < n) {                                  // warp-uniform branch
            float dd = g_dinv[d];
            acc = __ldg((const float4*)x + (size_t)d * 32 + lane);
            float ss = dd * dd;
            acc.x *= ss; acc.y *= ss; acc.z *= ss; acc.w *= ss;

            int beg = g_off[d], end = g_off[d + 1];
            int deg = end - beg;
            int dq = deg < 32 ? deg : 32;

            // lane-parallel prefetch: one coalesced idx read + parallel dinv gather
            if (lane < dq) {
                int s = __ldg(g_src_sorted + beg + lane);
                myidx[lane] = s;
                mynorm[lane] = g_dinv[s] * dd;
            }
            __syncwarp();

            int e = 0;
            for (; e + 4 <= dq; e += 4) {
                int s0 = myidx[e],     s1 = myidx[e + 1];
                int s2 = myidx[e + 2], s3 = myidx[e + 3];
                float n0 = mynorm[e],     n1 = mynorm[e + 1];
                float n2 = mynorm[e + 2], n3 = mynorm[e + 3];
                float4 v0 = __ldg((const float4*)x + (size_t)s0 * 32 + lane);
                float4 v1 = __ldg((const float4*)x + (size_t)s1 * 32 + lane);
                float4 v2 = __ldg((const float4*)x + (size_t)s2 * 32 + lane);
                float4 v3 = __ldg((const float4*)x + (size_t)s3 * 32 + lane);
                acc.x += v0.x * n0 + v1.x * n1 + v2.x * n2 + v3.x * n3;
                acc.y += v0.y * n0 + v1.y * n1 + v2.y * n2 + v3.y * n3;
                acc.z += v0.z * n0 + v1.z * n1 + v2.z * n2 + v3.z * n3;
                acc.w += v0.w * n0 + v1.w * n1 + v2.w * n2 + v3.w * n3;
            }
            for (; e < dq; e++) {
                int s0 = myidx[e];
                float n0 = mynorm[e];
                float4 v0 = __ldg((const float4*)x + (size_t)s0 * 32 + lane);
                acc.x += v0.x * n0; acc.y += v0.y * n0;
                acc.z += v0.z * n0; acc.w += v0.w * n0;
            }
            // rare tail: degree > 32
            for (int j = beg + 32; j < end; j++) {
                int s0 = __ldg(g_src_sorted + j);
                float n0 = g_dinv[s0] * dd;
                float4 v0 = __ldg((const float4*)x + (size_t)s0 * 32 + lane);
                acc.x += v0.x * n0; acc.y += v0.y * n0;
                acc.z += v0.z * n0; acc.w += v0.w * n0;
            }
            __syncwarp();   // scratch reuse safety for next row
        }
        *(float4*)&Ys[row * PITCH + lane * 4] =
            make_float4(tf32r(acc.x), tf32r(acc.y), tf32r(acc.z), tf32r(acc.w));
    }
    __syncthreads();

    // ---- dual tf32 MMA: 16 warps = (4m x 4n) ----
    int wm = wid >> 2, wn = wid & 3;
    int g  = lane >> 2, tig = lane & 3;

    float acc1[2][4][4];
    float acc2[2][4][4];
    #pragma unroll
    for (int mt = 0; mt < 2; mt++)
        #pragma unroll
        for (int nt = 0; nt < 4; nt++)
            #pragma unroll
            for (int q = 0; q < 4; q++) { acc1[mt][nt][q] = 0.f; acc2[mt][nt][q] = 0.f; }

    #pragma unroll 4
    for (int ks = 0; ks < 16; ks++) {
        int k0 = ks * 8;
        unsigned a[2][4];
        #pragma unroll
        for (int mt = 0; mt < 2; mt++) {
            int r = wm * 32 + mt * 16 + g;
            a[mt][0] = __float_as_uint(Ys[r * PITCH + k0 + tig]);
            a[mt][1] = __float_as_uint(Ys[(r + 8) * PITCH + k0 + tig]);
            a[mt][2] = __float_as_uint(Ys[r * PITCH + k0 + tig + 4]);
            a[mt][3] = __float_as_uint(Ys[(r + 8) * PITCH + k0 + tig + 4]);
        }
        #pragma unroll
        for (int nt = 0; nt < 4; nt++) {
            int nc = wn * 32 + nt * 8 + g;
            unsigned w1b0 = __float_as_uint(W1s[(k0 + tig) * PITCH + nc]);
            unsigned w1b1 = __float_as_uint(W1s[(k0 + tig + 4) * PITCH + nc]);
            unsigned w2b0 = __float_as_uint(W2s[(k0 + tig) * PITCH + nc]);
            unsigned w2b1 = __float_as_uint(W2s[(k0 + tig + 4) * PITCH + nc]);
            mma_tf32(acc1[0][nt], a[0], w1b0, w1b1);
            mma_tf32(acc1[1][nt], a[1], w1b0, w1b1);
            mma_tf32(acc2[0][nt], a[0], w2b0, w2b1);
            mma_tf32(acc2[1][nt], a[1], w2b0, w2b1);
        }
    }

    // ---- epilogue: bias + relu + mean, straight to gmem ----
    #pragma unroll
    for (int mt = 0; mt < 2; mt++) {
        int r0 = m0 + wm * 32 + mt * 16 + g;
        #pragma unroll
        for (int nt = 0; nt < 4; nt++) {
            int col = wn * 32 + nt * 8 + 2 * tig;
            float bb1x = __ldg(b1 + col), bb1y = __ldg(b1 + col + 1);
            float bb2x = __ldg(b2 + col), bb2y = __ldg(b2 + col + 1);
            if (r0 < n) {
                float2 o;
                o.x = 0.5f * (fmaxf(acc1[mt][nt][0] + bb1x, 0.f) +
                              fmaxf(acc2[mt][nt][0] + bb2x, 0.f));
                o.y = 0.5f * (fmaxf(acc1[mt][nt][1] + bb1y, 0.f) +
                              fmaxf(acc2[mt][nt][1] + bb2y, 0.f));
                *(float2*)(out + (size_t)r0 * 128 + col) = o;
            }
            if (r0 + 8 < n) {
                float2 o;
                o.x = 0.5f * (fmaxf(acc1[mt][nt][2] + bb1x, 0.f) +
                              fmaxf(acc2[mt][nt][2] + bb2x, 0.f));
                o.y = 0.5f * (fmaxf(acc1[mt][nt][3] + bb1y, 0.f) +
                              fmaxf(acc2[mt][nt][3] + bb2y, 0.f));
                *(float2*)(out + (size_t)(r0 + 8) * 128 + col) = o;
            }
        }
    }
}

extern "C" void kernel_launch(void* const* d_in, const int* in_sizes, int n_in,
                              void* d_out, int out_size) {
    const float* x  = (const float*)d_in[0];
    const int*   ei = (const int*)d_in[1];
    const float* W1 = (const float*)d_in[2];
    const float* b1 = (const float*)d_in[3];
    const float* W2 = (const float*)d_in[4];
    const float* b2 = (const float*)d_in[5];
    float* out = (float*)d_out;

    int n_nodes = in_sizes[0] / DD;       // 50000
    int n_edges = in_sizes[1] / 2;        // 600000
    const int* src = ei;
    const int* dst = ei + n_edges;

    int nb_nodes = (n_nodes + 255) / 256;
    int nb_e4    = ((n_edges + 3) / 4 + 255) / 256;
    int nscan    = (n_nodes + 1023) / 1024;

    k_hist<<<nb_e4, 256>>>(dst, n_edges);
    k_scan1<<<nscan, 1024>>>(n_nodes);
    k_scan23<<<nb_nodes, 256>>>(nscan, n_nodes);
    k_scatter<<<nb_e4, 256>>>(src, dst, n_edges);
    {
        int smem_bytes = 3 * 128 * PITCH * 4 + 16 * 32 * 8;   // 206848
        cudaFuncSetAttribute(k_mega,
                             cudaFuncAttributeMaxDynamicSharedMemorySize, smem_bytes);
        int gblocks = (n_nodes + BM - 1) / BM;
        k_mega<<<gblocks, 512, smem_bytes>>>(x, W1, b1, W2, b2, out, n_nodes);
    }
}

// round 8
// speedup vs baseline: 3.4632x; 1.0484x over previous
#include <cuda_runtime.h>

#define NN 50000
#define NE_MAX 700000
#define DD 128

// scratch (static __device__ — zero-initialized at module load)
__device__ int   g_cnt[NN];                 // in-degree histogram (re-zeroed by k_scan23)
__device__ int   g_off[NN + 1];             // CSR offsets
__device__ int   g_cur[NN];                 // scatter cursors
__device__ int   g_bsums[64];               // block sums for scan
__device__ float g_dinv[NN];                // 1/sqrt(deg+1)
__device__ int   g_src_sorted[NE_MAX];      // edge srcs sorted by dst
__device__ __align__(16) float g_y[(size_t)NN * DD];   // y = A_hat @ x

// ---------------- histogram ----------------
__global__ void k_hist(const int* __restrict__ dst, int e) {
    int i0 = (blockIdx.x * blockDim.x + threadIdx.x) * 4;
    if (i0 + 4 <= e) {
        int4 d4 = *(const int4*)(dst + i0);
        if ((unsigned)d4.x < NN) atomicAdd(&g_cnt[d4.x], 1);
        if ((unsigned)d4.y < NN) atomicAdd(&g_cnt[d4.y], 1);
        if ((unsigned)d4.z < NN) atomicAdd(&g_cnt[d4.z], 1);
        if ((unsigned)d4.w < NN) atomicAdd(&g_cnt[d4.w], 1);
    } else {
        for (int i = i0; i < e; i++) {
            unsigned d = (unsigned)dst[i];
            if (d < NN) atomicAdd(&g_cnt[d], 1);
        }
    }
}

// ---------------- scan phase 1 ----------------
__global__ void __launch_bounds__(1024) k_scan1(int n) {
    __shared__ int sm[1024];
    int tid = threadIdx.x;
    int gid = blockIdx.x * 1024 + tid;
    int v = (gid < n) ? g_cnt[gid] : 0;
    sm[tid] = v;
    __syncthreads();
    for (int ofs = 1; ofs < 1024; ofs <<= 1) {
        int t = (tid >= ofs) ? sm[tid - ofs] : 0;
        __syncthreads();
        sm[tid] += t;
        __syncthreads();
    }
    if (gid < n) g_off[gid] = sm[tid] - v;
    if (tid == 1023) g_bsums[blockIdx.x] = sm[1023];
}

// ---------------- scan 2+3 fused ----------------
__global__ void k_scan23(int nblocks, int n) {
    __shared__ int pre[65];
    int tid = threadIdx.x;
    if (tid == 0) {
        int run = 0;
        for (int i = 0; i < nblocks; i++) { int v = g_bsums[i]; pre[i] = run; run += v; }
        pre[nblocks] = run;
    }
    __syncthreads();
    int i = blockIdx.x * blockDim.x + tid;
    if (i < n) {
        int o = g_off[i] + pre[i >> 10];
        g_off[i] = o;
        g_cur[i] = o;
        g_dinv[i] = rsqrtf((float)g_cnt[i] + 1.0f);   // +1 self loop
        g_cnt[i] = 0;                                 // re-arm for next replay
    }
    if (i == 0) g_off[n] = pre[nblocks];
}

// ---------------- scatter ----------------
__global__ void k_scatter(const int* __restrict__ src, const int* __restrict__ dst, int e) {
    int i0 = (blockIdx.x * blockDim.x + threadIdx.x) * 4;
    if (i0 + 4 <= e) {
        int4 s4 = *(const int4*)(src + i0);
        int4 d4 = *(const int4*)(dst + i0);
        int p0 = -1, p1 = -1, p2 = -1, p3 = -1;
        if ((unsigned)s4.x < NN && (unsigned)d4.x < NN) p0 = atomicAdd(&g_cur[d4.x], 1);
        if ((unsigned)s4.y < NN && (unsigned)d4.y < NN) p1 = atomicAdd(&g_cur[d4.y], 1);
        if ((unsigned)s4.z < NN && (unsigned)d4.z < NN) p2 = atomicAdd(&g_cur[d4.z], 1);
        if ((unsigned)s4.w < NN && (unsigned)d4.w < NN) p3 = atomicAdd(&g_cur[d4.w], 1);
        if (p0 >= 0 && p0 < NE_MAX) g_src_sorted[p0] = s4.x;
        if (p1 >= 0 && p1 < NE_MAX) g_src_sorted[p1] = s4.y;
        if (p2 >= 0 && p2 < NE_MAX) g_src_sorted[p2] = s4.z;
        if (p3 >= 0 && p3 < NE_MAX) g_src_sorted[p3] = s4.w;
    } else {
        for (int i = i0; i < e; i++) {
            unsigned s = (unsigned)src[i], d = (unsigned)dst[i];
            if (s < NN && d < NN) {
                int p = atomicAdd(&g_cur[d], 1);
                if (p < NE_MAX) g_src_sorted[p] = (int)s;
            }
        }
    }
}

// ---------------- gather: warp/node, smem idx/norm prefetch, unroll 8 ------------
__global__ void __launch_bounds__(256) k_agg_gather(const float* __restrict__ x, int n) {
    __shared__ int   swidx[8 * 32];
    __shared__ float swnorm[8 * 32];
    int warp = (blockIdx.x * blockDim.x + threadIdx.x) >> 5;
    int wl   = (threadIdx.x >> 5) * 32;
    int lane = threadIdx.x & 31;
    if (warp >= n) return;
    int d = warp;

    float dd = g_dinv[d];
    float4 acc = __ldg((const float4*)x + (size_t)d * 32 + lane);
    float ss = dd * dd;
    acc.x *= ss; acc.y *= ss; acc.z *= ss; acc.w *= ss;

    int beg = g_off[d], end = g_off[d + 1];
    int deg = end - beg;
    int dq = deg < 32 ? deg : 32;

    if (lane < dq) {
        int s = __ldg(g_src_sorted + beg + lane);
        swidx[wl + lane] = s;
        swnorm[wl + lane] = g_dinv[s] * dd;
    }
    __syncwarp();

    int e = 0;
    for (; e + 8 <= dq; e += 8) {
        float4 v[8]; float nm[8];
        #pragma unroll
        for (int q = 0; q < 8; q++) {
            int s = swidx[wl + e + q];
            nm[q] = swnorm[wl + e + q];
            v[q] = __ldg((const float4*)x + (size_t)s * 32 + lane);
        }
        #pragma unroll
        for (int q = 0; q < 8; q++) {
            acc.x += v[q].x * nm[q]; acc.y += v[q].y * nm[q];
            acc.z += v[q].z * nm[q]; acc.w += v[q].w * nm[q];
        }
    }
    for (; e < dq; e++) {
        int s = swidx[wl + e];
        float nm = swnorm[wl + e];
        float4 v = __ldg((const float4*)x + (size_t)s * 32 + lane);
        acc.x += v.x * nm; acc.y += v.y * nm;
        acc.z += v.z * nm; acc.w += v.w * nm;
    }
    for (int j = beg + 32; j < end; j++) {        // rare tail deg>32
        int s = __ldg(g_src_sorted + j);
        float nm = g_dinv[s] * dd;
        float4 v = __ldg((const float4*)x + (size_t)s * 32 + lane);
        acc.x += v.x * nm; acc.y += v.y * nm;
        acc.z += v.z * nm; acc.w += v.w * nm;
    }
    ((float4*)g_y)[(size_t)d * 32 + lane] = acc;
}

// ---------------- persistent dual tf32 GEMM: weights staged ONCE per block -------
#define BM   128
#define PITCH 132
#define GEMM_GRID 148

__device__ __forceinline__ float tf32r(float f) {
    unsigned u;
    asm("cvt.rna.tf32.f32 %0, %1;" : "=r"(u) : "f"(f));
    return __uint_as_float(u);
}

__device__ __forceinline__ void mma_tf32(float* c, const unsigned* a,
                                         unsigned b0, unsigned b1) {
    asm volatile(
        "mma.sync.aligned.m16n8k8.row.col.f32.tf32.tf32.f32 "
        "{%0,%1,%2,%3}, {%4,%5,%6,%7}, {%8,%9}, {%0,%1,%2,%3};"
        : "+f"(c[0]), "+f"(c[1]), "+f"(c[2]), "+f"(c[3])
        : "r"(a[0]), "r"(a[1]), "r"(a[2]), "r"(a[3]), "r"(b0), "r"(b1));
}

__global__ void __launch_bounds__(512, 1)
k_gemm(const float* __restrict__ W1, const float* __restrict__ b1,
       const float* __restrict__ W2, const float* __restrict__ b2,
       float* __restrict__ out, int n, int ntiles) {
    extern __shared__ float smem[];
    float* W1s = smem;                       // 128 x PITCH
    float* W2s = smem + 128 * PITCH;         // 128 x PITCH
    float* Ys  = smem + 2 * 128 * PITCH;     // BM x PITCH

    int tid  = threadIdx.x;
    int lane = tid & 31;
    int wid  = tid >> 5;
    int wm = wid >> 2, wn = wid & 3;
    int g  = lane >> 2, tig = lane & 3;

    // stage weights once (tf32-rounded)
    for (int i = tid; i < 4096; i += 512) {
        int row = i >> 5, c4 = (i & 31) << 2;
        float4 v1 = ((const float4*)W1)[i];
        float4 v2 = ((const float4*)W2)[i];
        *(float4*)&W1s[row * PITCH + c4] =
            make_float4(tf32r(v1.x), tf32r(v1.y), tf32r(v1.z), tf32r(v1.w));
        *(float4*)&W2s[row * PITCH + c4] =
            make_float4(tf32r(v2.x), tf32r(v2.y), tf32r(v2.z), tf32r(v2.w));
    }

    for (int tile = blockIdx.x; tile < ntiles; tile += GEMM_GRID) {
        int m0 = tile * BM;
        __syncthreads();   // previous MMA reads of Ys done
        for (int i = tid; i < BM * 32; i += 512) {
            int row = i >> 5;
            int gg = m0 + row;
            float4 v = make_float4(0.f, 0.f, 0.f, 0.f);
            if (gg < n) v = ((const float4*)g_y)[(size_t)gg * 32 + (i & 31)];
            *(float4*)&Ys[row * PITCH + ((i & 31) << 2)] =
                make_float4(tf32r(v.x), tf32r(v.y), tf32r(v.z), tf32r(v.w));
        }
        __syncthreads();

        float acc1[2][4][4];
        float acc2[2][4][4];
        #pragma unroll
        for (int mt = 0; mt < 2; mt++)
            #pragma unroll
            for (int nt = 0; nt < 4; nt++)
                #pragma unroll
                for (int q = 0; q < 4; q++) { acc1[mt][nt][q] = 0.f; acc2[mt][nt][q] = 0.f; }

        #pragma unroll 4
        for (int ks = 0; ks < 16; ks++) {
            int k0 = ks * 8;
            unsigned a[2][4];
            #pragma unroll
            for (int mt = 0; mt < 2; mt++) {
                int r = wm * 32 + mt * 16 + g;
                a[mt][0] = __float_as_uint(Ys[r * PITCH + k0 + tig]);
                a[mt][1] = __float_as_uint(Ys[(r + 8) * PITCH + k0 + tig]);
                a[mt][2] = __float_as_uint(Ys[r * PITCH + k0 + tig + 4]);
                a[mt][3] = __float_as_uint(Ys[(r + 8) * PITCH + k0 + tig + 4]);
            }
            #pragma unroll
            for (int nt = 0; nt < 4; nt++) {
                int nc = wn * 32 + nt * 8 + g;
                unsigned w1b0 = __float_as_uint(W1s[(k0 + tig) * PITCH + nc]);
                unsigned w1b1 = __float_as_uint(W1s[(k0 + tig + 4) * PITCH + nc]);
                unsigned w2b0 = __float_as_uint(W2s[(k0 + tig) * PITCH + nc]);
                unsigned w2b1 = __float_as_uint(W2s[(k0 + tig + 4) * PITCH + nc]);
                mma_tf32(acc1[0][nt], a[0], w1b0, w1b1);
                mma_tf32(acc1[1][nt], a[1], w1b0, w1b1);
                mma_tf32(acc2[0][nt], a[0], w2b0, w2b1);
                mma_tf32(acc2[1][nt], a[1], w2b0, w2b1);
            }
        }

        #pragma unroll
        for (int mt = 0; mt < 2; mt++) {
            int r0 = m0 + wm * 32 + mt * 16 + g;
            #pragma unroll
            for (int nt = 0; nt < 4; nt++) {
                int col = wn * 32 + nt * 8 + 2 * tig;
                float bb1x = __ldg(b1 + col), bb1y = __ldg(b1 + col + 1);
                float bb2x = __ldg(b2 + col), bb2y = __ldg(b2 + col + 1);
                if (r0 < n) {
                    float2 o;
                    o.x = 0.5f * (fmaxf(acc1[mt][nt][0] + bb1x, 0.f) +
                                  fmaxf(acc2[mt][nt][0] + bb2x, 0.f));
                    o.y = 0.5f * (fmaxf(acc1[mt][nt][1] + bb1y, 0.f) +
                                  fmaxf(acc2[mt][nt][1] + bb2y, 0.f));
                    *(float2*)(out + (size_t)r0 * 128 + col) = o;
                }
                if (r0 + 8 < n) {
                    float2 o;
                    o.x = 0.5f * (fmaxf(acc1[mt][nt][2] + bb1x, 0.f) +
                                  fmaxf(acc2[mt][nt][2] + bb2x, 0.f));
                    o.y = 0.5f * (fmaxf(acc1[mt][nt][3] + bb1y, 0.f) +
                                  fmaxf(acc2[mt][nt][3] + bb2y, 0.f));
                    *(float2*)(out + (size_t)(r0 + 8) * 128 + col) = o;
                }
            }
        }
    }
}

extern "C" void kernel_launch(void* const* d_in, const int* in_sizes, int n_in,
                              void* d_out, int out_size) {
    const float* x  = (const float*)d_in[0];
    const int*   ei = (const int*)d_in[1];
    const float* W1 = (const float*)d_in[2];
    const float* b1 = (const float*)d_in[3];
    const float* W2 = (const float*)d_in[4];
    const float* b2 = (const float*)d_in[5];
    float* out = (float*)d_out;

    int n_nodes = in_sizes[0] / DD;       // 50000
    int n_edges = in_sizes[1] / 2;        // 600000
    const int* src = ei;
    const int* dst = ei + n_edges;

    int nb_nodes = (n_nodes + 255) / 256;
    int nb_e4    = ((n_edges + 3) / 4 + 255) / 256;
    int nscan    = (n_nodes + 1023) / 1024;

    k_hist<<<nb_e4, 256>>>(dst, n_edges);
    k_scan1<<<nscan, 1024>>>(n_nodes);
    k_scan23<<<nb_nodes, 256>>>(nscan, n_nodes);
    k_scatter<<<nb_e4, 256>>>(src, dst, n_edges);
    {
        int blocks = (n_nodes * 32 + 255) / 256;
        k_agg_gather<<<blocks, 256>>>(x, n_nodes);
    }
    {
        int smem_bytes = 3 * 128 * PITCH * 4;   // 202752
        cudaFuncSetAttribute(k_gemm,
                             cudaFuncAttributeMaxDynamicSharedMemorySize, smem_bytes);
        int ntiles = (n_nodes + BM - 1) / BM;
        k_gemm<<<GEMM_GRID, 512, smem_bytes>>>(W1, b1, W2, b2, out, n_nodes, ntiles);
    }
}

// round 10
// speedup vs baseline: 4.1687x; 1.2037x over previous
#include <cuda_runtime.h>
#include <cuda_fp16.h>
#include <string.h>

#define NN 50000
#define NE_MAX 700000
#define DD 128

// bit-reinterpretation helpers (the named intrinsics don't exist)
__device__ __forceinline__ unsigned h2_to_u(__half2 h) {
    unsigned u; memcpy(&u, &h, 4); return u;
}
__device__ __forceinline__ __half2 u_to_h2(unsigned u) {
    __half2 h; memcpy(&h, &u, 4); return h;
}

// scratch (static __device__ — zero-initialized at module load)
__device__ int   g_cnt[NN];                 // in-degree histogram (re-zeroed by k_scan23)
__device__ int   g_off[NN + 1];             // CSR offsets
__device__ int   g_cur[NN];                 // scatter cursors
__device__ int   g_bsums[64];               // block sums for scan
__device__ float g_dinv[NN];                // 1/sqrt(deg+1)
__device__ int   g_src_sorted[NE_MAX];      // edge srcs sorted by dst
__device__ __align__(16) __half g_xh[(size_t)NN * DD];   // x in fp16
__device__ __align__(16) __half g_yh[(size_t)NN * DD];   // y = A_hat @ x, fp16

// ---------------- prep: x -> fp16 conversion + degree histogram (fused) ----------
__global__ void k_prep(const float* __restrict__ x, const int* __restrict__ dst,
                       int e, int nf4) {
    int i = blockIdx.x * blockDim.x + threadIdx.x;
    if (i < nf4) {                       // nf4 = n*32 float4 groups
        float4 v = ((const float4*)x)[i];
        uint2 h;
        h.x = h2_to_u(__floats2half2_rn(v.x, v.y));
        h.y = h2_to_u(__floats2half2_rn(v.z, v.w));
        ((uint2*)g_xh)[i] = h;
    }
    int i0 = i * 4;
    if (i0 + 4 <= e) {
        int4 d4 = *(const int4*)(dst + i0);
        if ((unsigned)d4.x < NN) atomicAdd(&g_cnt[d4.x], 1);
        if ((unsigned)d4.y < NN) atomicAdd(&g_cnt[d4.y], 1);
        if ((unsigned)d4.z < NN) atomicAdd(&g_cnt[d4.z], 1);
        if ((unsigned)d4.w < NN) atomicAdd(&g_cnt[d4.w], 1);
    } else if (i0 < e) {
        for (int j = i0; j < e; j++) {
            unsigned d = (unsigned)dst[j];
            if (d < NN) atomicAdd(&g_cnt[d], 1);
        }
    }
}

// ---------------- scan phase 1 ----------------
__global__ void __launch_bounds__(1024) k_scan1(int n) {
    __shared__ int sm[1024];
    int tid = threadIdx.x;
    int gid = blockIdx.x * 1024 + tid;
    int v = (gid < n) ? g_cnt[gid] : 0;
    sm[tid] = v;
    __syncthreads();
    for (int ofs = 1; ofs < 1024; ofs <<= 1) {
        int t = (tid >= ofs) ? sm[tid - ofs] : 0;
        __syncthreads();
        sm[tid] += t;
        __syncthreads();
    }
    if (gid < n) g_off[gid] = sm[tid] - v;
    if (tid == 1023) g_bsums[blockIdx.x] = sm[1023];
}

// ---------------- scan 2+3 fused ----------------
__global__ void k_scan23(int nblocks, int n) {
    __shared__ int pre[65];
    int tid = threadIdx.x;
    if (tid == 0) {
        int run = 0;
        for (int i = 0; i < nblocks; i++) { int v = g_bsums[i]; pre[i] = run; run += v; }
        pre[nblocks] = run;
    }
    __syncthreads();
    int i = blockIdx.x * blockDim.x + tid;
    if (i < n) {
        int o = g_off[i] + pre[i >> 10];
        g_off[i] = o;
        g_cur[i] = o;
        g_dinv[i] = rsqrtf((float)g_cnt[i] + 1.0f);   // +1 self loop
        g_cnt[i] = 0;                                 // re-arm for next replay
    }
    if (i == 0) g_off[n] = pre[nblocks];
}

// ---------------- scatter ----------------
__global__ void k_scatter(const int* __restrict__ src, const int* __restrict__ dst, int e) {
    int i0 = (blockIdx.x * blockDim.x + threadIdx.x) * 4;
    if (i0 + 4 <= e) {
        int4 s4 = *(const int4*)(src + i0);
        int4 d4 = *(const int4*)(dst + i0);
        int p0 = -1, p1 = -1, p2 = -1, p3 = -1;
        if ((unsigned)s4.x < NN && (unsigned)d4.x < NN) p0 = atomicAdd(&g_cur[d4.x], 1);
        if ((unsigned)s4.y < NN && (unsigned)d4.y < NN) p1 = atomicAdd(&g_cur[d4.y], 1);
        if ((unsigned)s4.z < NN && (unsigned)d4.z < NN) p2 = atomicAdd(&g_cur[d4.z], 1);
        if ((unsigned)s4.w < NN && (unsigned)d4.w < NN) p3 = atomicAdd(&g_cur[d4.w], 1);
        if (p0 >= 0 && p0 < NE_MAX) g_src_sorted[p0] = s4.x;
        if (p1 >= 0 && p1 < NE_MAX) g_src_sorted[p1] = s4.y;
        if (p2 >= 0 && p2 < NE_MAX) g_src_sorted[p2] = s4.z;
        if (p3 >= 0 && p3 < NE_MAX) g_src_sorted[p3] = s4.w;
    } else {
        for (int i = i0; i < e; i++) {
            unsigned s = (unsigned)src[i], d = (unsigned)dst[i];
            if (s < NN && d < NN) {
                int p = atomicAdd(&g_cur[d], 1);
                if (p < NE_MAX) g_src_sorted[p] = (int)s;
            }
        }
    }
}

// ---------------- gather (fp16 x, fp32 accumulate, fp16 y out) -------------------
// warp/node; lane handles 4 cols (8 B); smem idx/norm prefetch; unroll 8
__global__ void __launch_bounds__(256) k_agg_gather(int n) {
    __shared__ int   swidx[8 * 32];
    __shared__ float swnorm[8 * 32];
    int warp = (blockIdx.x * blockDim.x + threadIdx.x) >> 5;
    int wl   = (threadIdx.x >> 5) * 32;
    int lane = threadIdx.x & 31;
    if (warp >= n) return;
    int d = warp;

    float dd = g_dinv[d];
    float ss = dd * dd;
    uint2 sh = __ldg((const uint2*)g_xh + (size_t)d * 32 + lane);
    float2 sa = __half22float2(u_to_h2(sh.x));
    float2 sb = __half22float2(u_to_h2(sh.y));
    float4 acc = make_float4(sa.x * ss, sa.y * ss, sb.x * ss, sb.y * ss);

    int beg = g_off[d], end = g_off[d + 1];
    int deg = end - beg;
    int dq = deg < 32 ? deg : 32;

    if (lane < dq) {
        int s = __ldg(g_src_sorted + beg + lane);
        swidx[wl + lane] = s;
        swnorm[wl + lane] = g_dinv[s] * dd;
    }
    __syncwarp();

    int e = 0;
    for (; e + 8 <= dq; e += 8) {
        uint2 v[8]; float nm[8];
        #pragma unroll
        for (int q = 0; q < 8; q++) {
            int s = swidx[wl + e + q];
            nm[q] = swnorm[wl + e + q];
            v[q] = __ldg((const uint2*)g_xh + (size_t)s * 32 + lane);
        }
        #pragma unroll
        for (int q = 0; q < 8; q++) {
            float2 a = __half22float2(u_to_h2(v[q].x));
            float2 b = __half22float2(u_to_h2(v[q].y));
            acc.x += a.x * nm[q]; acc.y += a.y * nm[q];
            acc.z += b.x * nm[q]; acc.w += b.y * nm[q];
        }
    }
    for (; e < dq; e++) {
        int s = swidx[wl + e];
        float nm = swnorm[wl + e];
        uint2 v = __ldg((const uint2*)g_xh + (size_t)s * 32 + lane);
        float2 a = __half22float2(u_to_h2(v.x));
        float2 b = __half22float2(u_to_h2(v.y));
        acc.x += a.x * nm; acc.y += a.y * nm;
        acc.z += b.x * nm; acc.w += b.y * nm;
    }
    for (int j = beg + 32; j < end; j++) {        // rare tail deg>32
        int s = __ldg(g_src_sorted + j);
        float nm = g_dinv[s] * dd;
        uint2 v = __ldg((const uint2*)g_xh + (size_t)s * 32 + lane);
        float2 a = __half22float2(u_to_h2(v.x));
        float2 b = __half22float2(u_to_h2(v.y));
        acc.x += a.x * nm; acc.y += a.y * nm;
        acc.z += b.x * nm; acc.w += b.y * nm;
    }
    uint2 o;
    o.x = h2_to_u(__floats2half2_rn(acc.x, acc.y));
    o.y = h2_to_u(__floats2half2_rn(acc.z, acc.w));
    ((uint2*)g_yh)[(size_t)d * 32 + lane] = o;
}

// ---------------- persistent dual fp16 MMA GEMM -----------------------------------
// out = 0.5*(relu(y@W1+b1)+relu(y@W2+b2)); weights staged transposed once per block
#define BM   128
#define PH   136        // half pitch: bank = 4g+tig = lane -> conflict-free quads
#define GEMM_GRID 148

__device__ __forceinline__ void mma_f16(float* c, const unsigned* a,
                                        unsigned b0, unsigned b1) {
    asm volatile(
        "mma.sync.aligned.m16n8k16.row.col.f32.f16.f16.f32 "
        "{%0,%1,%2,%3}, {%4,%5,%6,%7}, {%8,%9}, {%0,%1,%2,%3};"
        : "+f"(c[0]), "+f"(c[1]), "+f"(c[2]), "+f"(c[3])
        : "r"(a[0]), "r"(a[1]), "r"(a[2]), "r"(a[3]), "r"(b0), "r"(b1));
}

__global__ void __launch_bounds__(512, 1)
k_gemm(const float* __restrict__ W1, const float* __restrict__ b1,
       const float* __restrict__ W2, const float* __restrict__ b2,
       float* __restrict__ out, int n, int ntiles) {
    extern __shared__ __half smh[];
    __half* W1t = smh;                   // [n][k]: 128 x PH
    __half* W2t = smh + 128 * PH;        // 128 x PH
    __half* Ys  = smh + 2 * 128 * PH;    // [m][k]: BM x PH

    int tid  = threadIdx.x;
    int lane = tid & 31;
    int wid  = tid >> 5;
    int wm = wid >> 2, wn = wid & 3;
    int g  = lane >> 2, tig = lane & 3;

    // stage weights once, TRANSPOSED to [n][k] (B col-major needs contiguous k)
    for (int i = tid; i < 16384; i += 512) {
        int row = i >> 7, col = i & 127;    // W[k=row][n=col]
        W1t[col * PH + row] = __float2half(__ldg(W1 + i));
        W2t[col * PH + row] = __float2half(__ldg(W2 + i));
    }

    for (int tile = blockIdx.x; tile < ntiles; tile += GEMM_GRID) {
        int m0 = tile * BM;
        __syncthreads();   // previous MMA reads of Ys done (also covers weight staging)
        // stage y tile: pure fp16 copy, uint4 = 8 halves
        for (int i = tid; i < BM * 16; i += 512) {
            int row = i >> 4, c8 = (i & 15) * 8;
            int gg = m0 + row;
            uint4 v = make_uint4(0, 0, 0, 0);
            if (gg < n) v = ((const uint4*)g_yh)[(size_t)gg * 16 + (i & 15)];
            *(uint4*)&Ys[row * PH + c8] = v;
        }
        __syncthreads();

        float acc1[2][4][4];
        float acc2[2][4][4];
        #pragma unroll
        for (int mt = 0; mt < 2; mt++)
            #pragma unroll
            for (int nt = 0; nt < 4; nt++)
                #pragma unroll
                for (int q = 0; q < 4; q++) { acc1[mt][nt][q] = 0.f; acc2[mt][nt][q] = 0.f; }

        #pragma unroll
        for (int ks = 0; ks < 8; ks++) {
            int k0 = ks * 16;
            unsigned a[2][4];
            #pragma unroll
            for (int mt = 0; mt < 2; mt++) {
                int r = wm * 32 + mt * 16 + g;
                a[mt][0] = *(const unsigned*)&Ys[r * PH + k0 + 2 * tig];
                a[mt][1] = *(const unsigned*)&Ys[(r + 8) * PH + k0 + 2 * tig];
                a[mt][2] = *(const unsigned*)&Ys[r * PH + k0 + 8 + 2 * tig];
                a[mt][3] = *(const unsigned*)&Ys[(r + 8) * PH + k0 + 8 + 2 * tig];
            }
            #pragma unroll
            for (int nt = 0; nt < 4; nt++) {
                int nc = wn * 32 + nt * 8 + g;
                unsigned w1b0 = *(const unsigned*)&W1t[nc * PH + k0 + 2 * tig];
                unsigned w1b1 = *(const unsigned*)&W1t[nc * PH + k0 + 8 + 2 * tig];
                unsigned w2b0 = *(const unsigned*)&W2t[nc * PH + k0 + 2 * tig];
                unsigned w2b1 = *(const unsigned*)&W2t[nc * PH + k0 + 8 + 2 * tig];
                mma_f16(acc1[0][nt], a[0], w1b0, w1b1);
                mma_f16(acc1[1][nt], a[1], w1b0, w1b1);
                mma_f16(acc2[0][nt], a[0], w2b0, w2b1);
                mma_f16(acc2[1][nt], a[1], w2b0, w2b1);
            }
        }

        #pragma unroll
        for (int mt = 0; mt < 2; mt++) {
            int r0 = m0 + wm * 32 + mt * 16 + g;
            #pragma unroll
            for (int nt = 0; nt < 4; nt++) {
                int col = wn * 32 + nt * 8 + 2 * tig;
                float bb1x = __ldg(b1 + col), bb1y = __ldg(b1 + col + 1);
                float bb2x = __ldg(b2 + col), bb2y = __ldg(b2 + col + 1);
                if (r0 < n) {
                    float2 o;
                    o.x = 0.5f * (fmaxf(acc1[mt][nt][0] + bb1x, 0.f) +
                                  fmaxf(acc2[mt][nt][0] + bb2x, 0.f));
                    o.y = 0.5f * (fmaxf(acc1[mt][nt][1] + bb1y, 0.f) +
                                  fmaxf(acc2[mt][nt][1] + bb2y, 0.f));
                    *(float2*)(out + (size_t)r0 * 128 + col) = o;
                }
                if (r0 + 8 < n) {
                    float2 o;
                    o.x = 0.5f * (fmaxf(acc1[mt][nt][2] + bb1x, 0.f) +
                                  fmaxf(acc2[mt][nt][2] + bb2x, 0.f));
                    o.y = 0.5f * (fmaxf(acc1[mt][nt][3] + bb1y, 0.f) +
                                  fmaxf(acc2[mt][nt][3] + bb2y, 0.f));
                    *(float2*)(out + (size_t)(r0 + 8) * 128 + col) = o;
                }
            }
        }
    }
}

extern "C" void kernel_launch(void* const* d_in, const int* in_sizes, int n_in,
                              void* d_out, int out_size) {
    const float* x  = (const float*)d_in[0];
    const int*   ei = (const int*)d_in[1];
    const float* W1 = (const float*)d_in[2];
    const float* b1 = (const float*)d_in[3];
    const float* W2 = (const float*)d_in[4];
    const float* b2 = (const float*)d_in[5];
    float* out = (float*)d_out;

    int n_nodes = in_sizes[0] / DD;       // 50000
    int n_edges = in_sizes[1] / 2;        // 600000
    const int* src = ei;
    const int* dst = ei + n_edges;

    int nb_nodes = (n_nodes + 255) / 256;
    int nb_e4    = ((n_edges + 3) / 4 + 255) / 256;
    int nscan    = (n_nodes + 1023) / 1024;
    int nf4      = n_nodes * 32;          // float4 groups in x
    int nb_prep  = (nf4 + 255) / 256;     // covers both convert + hist ranges

    k_prep<<<nb_prep, 256>>>(x, dst, n_edges, nf4);
    k_scan1<<<nscan, 1024>>>(n_nodes);
    k_scan23<<<nb_nodes, 256>>>(nscan, n_nodes);
    k_scatter<<<nb_e4, 256>>>(src, dst, n_edges);
    {
        int blocks = (n_nodes * 32 + 255) / 256;
        k_agg_gather<<<blocks, 256>>>(n_nodes);
    }
    {
        int smem_bytes = 3 * 128 * PH * 2;   // 104448
        cudaFuncSetAttribute(k_gemm,
                             cudaFuncAttributeMaxDynamicSharedMemorySize, smem_bytes);
        int ntiles = (n_nodes + BM - 1) / BM;
        k_gemm<<<GEMM_GRID, 512, smem_bytes>>>(W1, b1, W2, b2, out, n_nodes, ntiles);
    }
}

// round 11
// speedup vs baseline: 4.5858x; 1.1000x over previous
#include <cuda_runtime.h>
#include <cuda_fp16.h>
#include <string.h>

#define NN 50000
#define DD 128
#define CAP 128        // per-node bucket capacity; P(Poisson(12) > 128) ~ 1e-80

// bit-reinterpretation helpers
__device__ __forceinline__ unsigned h2_to_u(__half2 h) {
    unsigned u; memcpy(&u, &h, 4); return u;
}
__device__ __forceinline__ __half2 u_to_h2(unsigned u) {
    __half2 h; memcpy(&h, &u, 4); return h;
}

// scratch (static __device__ — zero-initialized at module load)
__device__ int   g_cnt[NN];                  // bucket cursors / degree (re-zeroed by k_dinv)
__device__ int   g_deg[NN];                  // degree snapshot for gather
__device__ float g_dinv[NN];                 // 1/sqrt(deg+1)
__device__ int   g_bucket[(size_t)NN * CAP]; // per-dst src lists (fixed stride)
__device__ __align__(16) __half g_xh[(size_t)NN * DD];   // x in fp16
__device__ __align__(16) __half g_yh[(size_t)NN * DD];   // y = A_hat @ x, fp16

// ---------------- prep: x -> fp16 ----------------
__global__ void k_prep(const float* __restrict__ x, int nf4) {
    int i = blockIdx.x * blockDim.x + threadIdx.x;
    if (i < nf4) {                       // nf4 = n*32 float4 groups
        float4 v = ((const float4*)x)[i];
        uint2 h;
        h.x = h2_to_u(__floats2half2_rn(v.x, v.y));
        h.y = h2_to_u(__floats2half2_rn(v.z, v.w));
        ((uint2*)g_xh)[i] = h;
    }
}

// ---------------- scatter: single atomic per edge, direct bucket placement -------
__global__ void k_scatter(const int* __restrict__ src, const int* __restrict__ dst, int e) {
    int i0 = (blockIdx.x * blockDim.x + threadIdx.x) * 4;
    if (i0 + 4 <= e) {
        int4 s4 = *(const int4*)(src + i0);
        int4 d4 = *(const int4*)(dst + i0);
        int p0 = -1, p1 = -1, p2 = -1, p3 = -1;
        if ((unsigned)s4.x < NN && (unsigned)d4.x < NN) p0 = atomicAdd(&g_cnt[d4.x], 1);
        if ((unsigned)s4.y < NN && (unsigned)d4.y < NN) p1 = atomicAdd(&g_cnt[d4.y], 1);
        if ((unsigned)s4.z < NN && (unsigned)d4.z < NN) p2 = atomicAdd(&g_cnt[d4.z], 1);
        if ((unsigned)s4.w < NN && (unsigned)d4.w < NN) p3 = atomicAdd(&g_cnt[d4.w], 1);
        if (p0 >= 0 && p0 < CAP) g_bucket[(size_t)d4.x * CAP + p0] = s4.x;
        if (p1 >= 0 && p1 < CAP) g_bucket[(size_t)d4.y * CAP + p1] = s4.y;
        if (p2 >= 0 && p2 < CAP) g_bucket[(size_t)d4.z * CAP + p2] = s4.z;
        if (p3 >= 0 && p3 < CAP) g_bucket[(size_t)d4.w * CAP + p3] = s4.w;
    } else {
        for (int i = i0; i < e; i++) {
            unsigned s = (unsigned)src[i], d = (unsigned)dst[i];
            if (s < NN && d < NN) {
                int p = atomicAdd(&g_cnt[d], 1);
                if (p < CAP) g_bucket[(size_t)d * CAP + p] = (int)s;
            }
        }
    }
}

// ---------------- dinv + degree snapshot + cursor re-arm ----------------
__global__ void k_dinv(int n) {
    int i = blockIdx.x * blockDim.x + threadIdx.x;
    if (i < n) {
        int c = g_cnt[i];
        g_deg[i] = c < CAP ? c : CAP;
        g_dinv[i] = rsqrtf((float)c + 1.0f);   // +1 self loop
        g_cnt[i] = 0;                          // re-arm for next graph replay
    }
}

// ---------------- gather (fp16 x, fp32 accumulate, fp16 y out) -------------------
// warp/node; lane handles 4 cols (8 B); smem idx/norm prefetch; unroll 8
__global__ void __launch_bounds__(256) k_agg_gather(int n) {
    __shared__ int   swidx[8 * 32];
    __shared__ float swnorm[8 * 32];
    int warp = (blockIdx.x * blockDim.x + threadIdx.x) >> 5;
    int wl   = (threadIdx.x >> 5) * 32;
    int lane = threadIdx.x & 31;
    if (warp >= n) return;
    int d = warp;

    float dd = g_dinv[d];
    float ss = dd * dd;
    uint2 sh = __ldg((const uint2*)g_xh + (size_t)d * 32 + lane);
    float2 sa = __half22float2(u_to_h2(sh.x));
    float2 sb = __half22float2(u_to_h2(sh.y));
    float4 acc = make_float4(sa.x * ss, sa.y * ss, sb.x * ss, sb.y * ss);

    int deg = g_deg[d];
    const int* bkt = g_bucket + (size_t)d * CAP;
    int dq = deg < 32 ? deg : 32;

    if (lane < dq) {
        int s = __ldg(bkt + lane);
        swidx[wl + lane] = s;
        swnorm[wl + lane] = g_dinv[s] * dd;
    }
    __syncwarp();

    int e = 0;
    for (; e + 8 <= dq; e += 8) {
        uint2 v[8]; float nm[8];
        #pragma unroll
        for (int q = 0; q < 8; q++) {
            int s = swidx[wl + e + q];
            nm[q] = swnorm[wl + e + q];
            v[q] = __ldg((const uint2*)g_xh + (size_t)s * 32 + lane);
        }
        #pragma unroll
        for (int q = 0; q < 8; q++) {
            float2 a = __half22float2(u_to_h2(v[q].x));
            float2 b = __half22float2(u_to_h2(v[q].y));
            acc.x += a.x * nm[q]; acc.y += a.y * nm[q];
            acc.z += b.x * nm[q]; acc.w += b.y * nm[q];
        }
    }
    for (; e < dq; e++) {
        int s = swidx[wl + e];
        float nm = swnorm[wl + e];
        uint2 v = __ldg((const uint2*)g_xh + (size_t)s * 32 + lane);
        float2 a = __half22float2(u_to_h2(v.x));
        float2 b = __half22float2(u_to_h2(v.y));
        acc.x += a.x * nm; acc.y += a.y * nm;
        acc.z += b.x * nm; acc.w += b.y * nm;
    }
    for (int j = 32; j < deg; j++) {          // rare tail deg>32
        int s = __ldg(bkt + j);
        float nm = g_dinv[s] * dd;
        uint2 v = __ldg((const uint2*)g_xh + (size_t)s * 32 + lane);
        float2 a = __half22float2(u_to_h2(v.x));
        float2 b = __half22float2(u_to_h2(v.y));
        acc.x += a.x * nm; acc.y += a.y * nm;
        acc.z += b.x * nm; acc.w += b.y * nm;
    }
    uint2 o;
    o.x = h2_to_u(__floats2half2_rn(acc.x, acc.y));
    o.y = h2_to_u(__floats2half2_rn(acc.z, acc.w));
    ((uint2*)g_yh)[(size_t)d * 32 + lane] = o;
}

// ---------------- persistent dual fp16 MMA GEMM -----------------------------------
#define BM   128
#define PH   136        // half pitch: conflict-free quad access
#define GEMM_GRID 148

__device__ __forceinline__ void mma_f16(float* c, const unsigned* a,
                                        unsigned b0, unsigned b1) {
    asm volatile(
        "mma.sync.aligned.m16n8k16.row.col.f32.f16.f16.f32 "
        "{%0,%1,%2,%3}, {%4,%5,%6,%7}, {%8,%9}, {%0,%1,%2,%3};"
        : "+f"(c[0]), "+f"(c[1]), "+f"(c[2]), "+f"(c[3])
        : "r"(a[0]), "r"(a[1]), "r"(a[2]), "r"(a[3]), "r"(b0), "r"(b1));
}

__global__ void __launch_bounds__(512, 1)
k_gemm(const float* __restrict__ W1, const float* __restrict__ b1,
       const float* __restrict__ W2, const float* __restrict__ b2,
       float* __restrict__ out, int n, int ntiles) {
    extern __shared__ __half smh[];
    __half* W1t = smh;                   // [n][k]: 128 x PH
    __half* W2t = smh + 128 * PH;        // 128 x PH
    __half* Ys  = smh + 2 * 128 * PH;    // [m][k]: BM x PH

    int tid  = threadIdx.x;
    int lane = tid & 31;
    int wid  = tid >> 5;
    int wm = wid >> 2, wn = wid & 3;
    int g  = lane >> 2, tig = lane & 3;

    // stage weights once, TRANSPOSED to [n][k]
    for (int i = tid; i < 16384; i += 512) {
        int row = i >> 7, col = i & 127;    // W[k=row][n=col]
        W1t[col * PH + row] = __float2half(__ldg(W1 + i));
        W2t[col * PH + row] = __float2half(__ldg(W2 + i));
    }

    for (int tile = blockIdx.x; tile < ntiles; tile += GEMM_GRID) {
        int m0 = tile * BM;
        __syncthreads();   // previous MMA reads of Ys done (also covers weight staging)
        for (int i = tid; i < BM * 16; i += 512) {
            int row = i >> 4, c8 = (i & 15) * 8;
            int gg = m0 + row;
            uint4 v = make_uint4(0, 0, 0, 0);
            if (gg < n) v = ((const uint4*)g_yh)[(size_t)gg * 16 + (i & 15)];
            *(uint4*)&Ys[row * PH + c8] = v;
        }
        __syncthreads();

        float acc1[2][4][4];
        float acc2[2][4][4];
        #pragma unroll
        for (int mt = 0; mt < 2; mt++)
            #pragma unroll
            for (int nt = 0; nt < 4; nt++)
                #pragma unroll
                for (int q = 0; q < 4; q++) { acc1[mt][nt][q] = 0.f; acc2[mt][nt][q] = 0.f; }

        #pragma unroll
        for (int ks = 0; ks < 8; ks++) {
            int k0 = ks * 16;
            unsigned a[2][4];
            #pragma unroll
            for (int mt = 0; mt < 2; mt++) {
                int r = wm * 32 + mt * 16 + g;
                a[mt][0] = *(const unsigned*)&Ys[r * PH + k0 + 2 * tig];
                a[mt][1] = *(const unsigned*)&Ys[(r + 8) * PH + k0 + 2 * tig];
                a[mt][2] = *(const unsigned*)&Ys[r * PH + k0 + 8 + 2 * tig];
                a[mt][3] = *(const unsigned*)&Ys[(r + 8) * PH + k0 + 8 + 2 * tig];
            }
            #pragma unroll
            for (int nt = 0; nt < 4; nt++) {
                int nc = wn * 32 + nt * 8 + g;
                unsigned w1b0 = *(const unsigned*)&W1t[nc * PH + k0 + 2 * tig];
                unsigned w1b1 = *(const unsigned*)&W1t[nc * PH + k0 + 8 + 2 * tig];
                unsigned w2b0 = *(const unsigned*)&W2t[nc * PH + k0 + 2 * tig];
                unsigned w2b1 = *(const unsigned*)&W2t[nc * PH + k0 + 8 + 2 * tig];
                mma_f16(acc1[0][nt], a[0], w1b0, w1b1);
                mma_f16(acc1[1][nt], a[1], w1b0, w1b1);
                mma_f16(acc2[0][nt], a[0], w2b0, w2b1);
                mma_f16(acc2[1][nt], a[1], w2b0, w2b1);
            }
        }

        #pragma unroll
        for (int mt = 0; mt < 2; mt++) {
            int r0 = m0 + wm * 32 + mt * 16 + g;
            #pragma unroll
            for (int nt = 0; nt < 4; nt++) {
                int col = wn * 32 + nt * 8 + 2 * tig;
                float bb1x = __ldg(b1 + col), bb1y = __ldg(b1 + col + 1);
                float bb2x = __ldg(b2 + col), bb2y = __ldg(b2 + col + 1);
                if (r0 < n) {
                    float2 o;
                    o.x = 0.5f * (fmaxf(acc1[mt][nt][0] + bb1x, 0.f) +
                                  fmaxf(acc2[mt][nt][0] + bb2x, 0.f));
                    o.y = 0.5f * (fmaxf(acc1[mt][nt][1] + bb1y, 0.f) +
                                  fmaxf(acc2[mt][nt][1] + bb2y, 0.f));
                    *(float2*)(out + (size_t)r0 * 128 + col) = o;
                }
                if (r0 + 8 < n) {
                    float2 o;
                    o.x = 0.5f * (fmaxf(acc1[mt][nt][2] + bb1x, 0.f) +
                                  fmaxf(acc2[mt][nt][2] + bb2x, 0.f));
                    o.y = 0.5f * (fmaxf(acc1[mt][nt][3] + bb1y, 0.f) +
                                  fmaxf(acc2[mt][nt][3] + bb2y, 0.f));
                    *(float2*)(out + (size_t)(r0 + 8) * 128 + col) = o;
                }
            }
        }
    }
}

extern "C" void kernel_launch(void* const* d_in, const int* in_sizes, int n_in,
                              void* d_out, int out_size) {
    const float* x  = (const float*)d_in[0];
    const int*   ei = (const int*)d_in[1];
    const float* W1 = (const float*)d_in[2];
    const float* b1 = (const float*)d_in[3];
    const float* W2 = (const float*)d_in[4];
    const float* b2 = (const float*)d_in[5];
    float* out = (float*)d_out;

    int n_nodes = in_sizes[0] / DD;       // 50000
    int n_edges = in_sizes[1] / 2;        // 600000
    const int* src = ei;
    const int* dst = ei + n_edges;

    int nb_nodes = (n_nodes + 255) / 256;
    int nb_e4    = ((n_edges + 3) / 4 + 255) / 256;
    int nf4      = n_nodes * 32;          // float4 groups in x
    int nb_prep  = (nf4 + 255) / 256;

    k_prep<<<nb_prep, 256>>>(x, nf4);
    k_scatter<<<nb_e4, 256>>>(src, dst, n_edges);
    k_dinv<<<nb_nodes, 256>>>(n_nodes);
    {
        int blocks = (n_nodes * 32 + 255) / 256;
        k_agg_gather<<<blocks, 256>>>(n_nodes);
    }
    {
        int smem_bytes = 3 * 128 * PH * 2;   // 104448
        cudaFuncSetAttribute(k_gemm,
                             cudaFuncAttributeMaxDynamicSharedMemorySize, smem_bytes);
        int ntiles = (n_nodes + BM - 1) / BM;
        k_gemm<<<GEMM_GRID, 512, smem_bytes>>>(W1, b1, W2, b2, out, n_nodes, ntiles);
    }
}

// round 13
// speedup vs baseline: 5.0956x; 1.1112x over previous
#include <cuda_runtime.h>
#include <cuda_fp16.h>
#include <string.h>

#define NN 50000
#define DD 128
#define CAP 128        // per-node bucket capacity; P(Poisson(12) > 128) ~ 1e-80

// bit-reinterpretation helpers
__device__ __forceinline__ unsigned h2_to_u(__half2 h) {
    unsigned u; memcpy(&u, &h, 4); return u;
}
__device__ __forceinline__ __half2 u_to_h2(unsigned u) {
    __half2 h; memcpy(&h, &u, 4); return h;
}
// packed fp32x2 helpers (Blackwell FFMA2 path)
__device__ __forceinline__ unsigned long long packf2(float lo, float hi) {
    unsigned long long r;
    asm("mov.b64 %0, {%1, %2};" : "=l"(r) : "f"(lo), "f"(hi));
    return r;
}
__device__ __forceinline__ void unpackf2(unsigned long long v, float& lo, float& hi) {
    asm("mov.b64 {%0, %1}, %2;" : "=f"(lo), "=f"(hi) : "l"(v));
}
__device__ __forceinline__ void ffma2p(unsigned long long& d,
                                       unsigned long long a, unsigned long long b) {
    asm("fma.rn.f32x2 %0, %1, %2, %0;" : "+l"(d) : "l"(a), "l"(b));
}

// scratch (static __device__ — zero-initialized at module load)
__device__ int   g_cnt[NN];                  // bucket cursors / degree (re-zeroed by k_dinv)
__device__ int   g_deg[NN];                  // degree snapshot for gather
__device__ float g_dinv[NN];                 // 1/sqrt(deg+1)
__device__ int   g_bucket[(size_t)NN * CAP]; // per-dst src lists (fixed stride)
__device__ __align__(16) __half g_xh[(size_t)NN * DD];   // x in fp16
__device__ __align__(16) __half g_yh[(size_t)NN * DD];   // y = A_hat @ x, fp16

// ---------------- prep + scatter fused: x->fp16 convert, edge bucket placement ---
__global__ void k_prepscatter(const float* __restrict__ x, int nf4,
                              const int* __restrict__ src,
                              const int* __restrict__ dst, int e) {
    int i = blockIdx.x * blockDim.x + threadIdx.x;
    if (i < nf4) {                       // nf4 = n*32 float4 groups
        float4 v = ((const float4*)x)[i];
        uint2 h;
        h.x = h2_to_u(__floats2half2_rn(v.x, v.y));
        h.y = h2_to_u(__floats2half2_rn(v.z, v.w));
        ((uint2*)g_xh)[i] = h;
    }
    int i0 = i * 4;
    if (i0 + 4 <= e) {
        int4 s4 = *(const int4*)(src + i0);
        int4 d4 = *(const int4*)(dst + i0);
        int p0 = -1, p1 = -1, p2 = -1, p3 = -1;
        if ((unsigned)s4.x < NN && (unsigned)d4.x < NN) p0 = atomicAdd(&g_cnt[d4.x], 1);
        if ((unsigned)s4.y < NN && (unsigned)d4.y < NN) p1 = atomicAdd(&g_cnt[d4.y], 1);
        if ((unsigned)s4.z < NN && (unsigned)d4.z < NN) p2 = atomicAdd(&g_cnt[d4.z], 1);
        if ((unsigned)s4.w < NN && (unsigned)d4.w < NN) p3 = atomicAdd(&g_cnt[d4.w], 1);
        if (p0 >= 0 && p0 < CAP) g_bucket[(size_t)d4.x * CAP + p0] = s4.x;
        if (p1 >= 0 && p1 < CAP) g_bucket[(size_t)d4.y * CAP + p1] = s4.y;
        if (p2 >= 0 && p2 < CAP) g_bucket[(size_t)d4.z * CAP + p2] = s4.z;
        if (p3 >= 0 && p3 < CAP) g_bucket[(size_t)d4.w * CAP + p3] = s4.w;
    } else if (i0 < e) {
        for (int j = i0; j < e; j++) {
            unsigned s = (unsigned)src[j], d = (unsigned)dst[j];
            if (s < NN && d < NN) {
                int p = atomicAdd(&g_cnt[d], 1);
                if (p < CAP) g_bucket[(size_t)d * CAP + p] = (int)s;
            }
        }
    }
}

// ---------------- dinv + degree snapshot + cursor re-arm ----------------
__global__ void k_dinv(int n) {
    int i = blockIdx.x * blockDim.x + threadIdx.x;
    if (i < n) {
        int c = g_cnt[i];
        g_deg[i] = c < CAP ? c : CAP;
        g_dinv[i] = rsqrtf((float)c + 1.0f);   // +1 self loop
        g_cnt[i] = 0;                          // re-arm for next graph replay
    }
}

// ---------------- gather (fp16 x, packed fp32x2 accumulate, fp16 y out) ----------
// warp/node; lane handles 4 cols (8 B); smem idx/norm prefetch; unroll 8
__global__ void __launch_bounds__(256) k_agg_gather(int n) {
    __shared__ int   swidx[8 * 32];
    __shared__ float swnorm[8 * 32];
    int warp = (blockIdx.x * blockDim.x + threadIdx.x) >> 5;
    int wl   = (threadIdx.x >> 5) * 32;
    int lane = threadIdx.x & 31;
    if (warp >= n) return;
    int d = warp;

    float dd = g_dinv[d];
    float ss = dd * dd;
    uint2 sh = __ldg((const uint2*)g_xh + (size_t)d * 32 + lane);
    float2 sa = __half22float2(u_to_h2(sh.x));
    float2 sb = __half22float2(u_to_h2(sh.y));
    unsigned long long acc01 = packf2(sa.x * ss, sa.y * ss);
    unsigned long long acc23 = packf2(sb.x * ss, sb.y * ss);

    int deg = g_deg[d];
    const int* bkt = g_bucket + (size_t)d * CAP;
    int dq = deg < 32 ? deg : 32;

    if (lane < dq) {
        int s = __ldg(bkt + lane);
        swidx[wl + lane] = s;
        swnorm[wl + lane] = g_dinv[s] * dd;
    }
    __syncwarp();

    int e = 0;
    for (; e + 8 <= dq; e += 8) {
        uint2 v[8]; float nm[8];
        #pragma unroll
        for (int q = 0; q < 8; q++) {
            int s = swidx[wl + e + q];
            nm[q] = swnorm[wl + e + q];
            v[q] = __ldg((const uint2*)g_xh + (size_t)s * 32 + lane);
        }
        #pragma unroll
        for (int q = 0; q < 8; q++) {
            float2 a = __half22float2(u_to_h2(v[q].x));
            float2 b = __half22float2(u_to_h2(v[q].y));
            unsigned long long nm2 = packf2(nm[q], nm[q]);
            ffma2p(acc01, packf2(a.x, a.y), nm2);
            ffma2p(acc23, packf2(b.x, b.y), nm2);
        }
    }
    for (; e < dq; e++) {
        int s = swidx[wl + e];
        float nmv = swnorm[wl + e];
        uint2 v = __ldg((const uint2*)g_xh + (size_t)s * 32 + lane);
        float2 a = __half22float2(u_to_h2(v.x));
        float2 b = __half22float2(u_to_h2(v.y));
        unsigned long long nm2 = packf2(nmv, nmv);
        ffma2p(acc01, packf2(a.x, a.y), nm2);
        ffma2p(acc23, packf2(b.x, b.y), nm2);
    }
    for (int j = 32; j < deg; j++) {          // rare tail deg>32
        int s = __ldg(bkt + j);
        float nmv = g_dinv[s] * dd;
        uint2 v = __ldg((const uint2*)g_xh + (size_t)s * 32 + lane);
        float2 a = __half22float2(u_to_h2(v.x));
        float2 b = __half22float2(u_to_h2(v.y));
        unsigned long long nm2 = packf2(nmv, nmv);
        ffma2p(acc01, packf2(a.x, a.y), nm2);
        ffma2p(acc23, packf2(b.x, b.y), nm2);
    }
    float a0, a1, a2, a3;
    unpackf2(acc01, a0, a1);
    unpackf2(acc23, a2, a3);
    uint2 o;
    o.x = h2_to_u(__floats2half2_rn(a0, a1));
    o.y = h2_to_u(__floats2half2_rn(a2, a3));
    ((uint2*)g_yh)[(size_t)d * 32 + lane] = o;
}

// ---------------- persistent dual fp16 MMA GEMM -----------------------------------
#define BM   128
#define PH   136        // half pitch: conflict-free quad access
#define GEMM_GRID 148

__device__ __forceinline__ void mma_f16(float* c, const unsigned* a,
                                        unsigned b0, unsigned b1) {
    asm volatile(
        "mma.sync.aligned.m16n8k16.row.col.f32.f16.f16.f32 "
        "{%0,%1,%2,%3}, {%4,%5,%6,%7}, {%8,%9}, {%0,%1,%2,%3};"
        : "+f"(c[0]), "+f"(c[1]), "+f"(c[2]), "+f"(c[3])
        : "r"(a[0]), "r"(a[1]), "r"(a[2]), "r"(a[3]), "r"(b0), "r"(b1));
}

__global__ void __launch_bounds__(512, 1)
k_gemm(const float* __restrict__ W1, const float* __restrict__ b1,
       const float* __restrict__ W2, const float* __restrict__ b2,
       float* __restrict__ out, int n, int ntiles) {
    extern __shared__ __half smh[];
    __half* W1t = smh;                   // [n][k]: 128 x PH
    __half* W2t = smh + 128 * PH;        // 128 x PH
    __half* Ys  = smh + 2 * 128 * PH;    // [m][k]: BM x PH

    int tid  = threadIdx.x;
    int lane = tid & 31;
    int wid  = tid >> 5;
    int wm = wid >> 2, wn = wid & 3;
    int g  = lane >> 2, tig = lane & 3;

    // stage weights once, TRANSPOSED to [n][k]
    for (int i = tid; i < 16384; i += 512) {
        int row = i >> 7, col = i & 127;    // W[k=row][n=col]
        W1t[col * PH + row] = __float2half(__ldg(W1 + i));
        W2t[col * PH + row] = __float2half(__ldg(W2 + i));
    }

    for (int tile = blockIdx.x; tile < ntiles; tile += GEMM_GRID) {
        int m0 = tile * BM;
        __syncthreads();   // previous MMA reads of Ys done (also covers weight staging)
        for (int i = tid; i < BM * 16; i += 512) {
            int row = i >> 4, c8 = (i & 15) * 8;
            int gg = m0 + row;
            uint4 v = make_uint4(0, 0, 0, 0);
            if (gg < n) v = ((const uint4*)g_yh)[(size_t)gg * 16 + (i & 15)];
            *(uint4*)&Ys[row * PH + c8] = v;
        }
        __syncthreads();

        float acc1[2][4][4];
        float acc2[2][4][4];
        #pragma unroll
        for (int mt = 0; mt < 2; mt++)
            #pragma unroll
            for (int nt = 0; nt < 4; nt++)
                #pragma unroll
                for (int q = 0; q < 4; q++) { acc1[mt][nt][q] = 0.f; acc2[mt][nt][q] = 0.f; }

        #pragma unroll
        for (int ks = 0; ks < 8; ks++) {
            int k0 = ks * 16;
            unsigned a[2][4];
            #pragma unroll
            for (int mt = 0; mt < 2; mt++) {
                int r = wm * 32 + mt * 16 + g;
                a[mt][0] = *(const unsigned*)&Ys[r * PH + k0 + 2 * tig];
                a[mt][1] = *(const unsigned*)&Ys[(r + 8) * PH + k0 + 2 * tig];
                a[mt][2] = *(const unsigned*)&Ys[r * PH + k0 + 8 + 2 * tig];
                a[mt][3] = *(const unsigned*)&Ys[(r + 8) * PH + k0 + 8 + 2 * tig];
            }
            #pragma unroll
            for (int nt = 0; nt < 4; nt++) {
                int nc = wn * 32 + nt * 8 + g;
                unsigned w1b0 = *(const unsigned*)&W1t[nc * PH + k0 + 2 * tig];
                unsigned w1b1 = *(const unsigned*)&W1t[nc * PH + k0 + 8 + 2 * tig];
                unsigned w2b0 = *(const unsigned*)&W2t[nc * PH + k0 + 2 * tig];
                unsigned w2b1 = *(const unsigned*)&W2t[nc * PH + k0 + 8 + 2 * tig];
                mma_f16(acc1[0][nt], a[0], w1b0, w1b1);
                mma_f16(acc1[1][nt], a[1], w1b0, w1b1);
                mma_f16(acc2[0][nt], a[0], w2b0, w2b1);
                mma_f16(acc2[1][nt], a[1], w2b0, w2b1);
            }
        }

        #pragma unroll
        for (int mt = 0; mt < 2; mt++) {
            int r0 = m0 + wm * 32 + mt * 16 + g;
            #pragma unroll
            for (int nt = 0; nt < 4; nt++) {
                int col = wn * 32 + nt * 8 + 2 * tig;
                float bb1x = __ldg(b1 + col), bb1y = __ldg(b1 + col + 1);
                float bb2x = __ldg(b2 + col), bb2y = __ldg(b2 + col + 1);
                if (r0 < n) {
                    float2 o;
                    o.x = 0.5f * (fmaxf(acc1[mt][nt][0] + bb1x, 0.f) +
                                  fmaxf(acc2[mt][nt][0] + bb2x, 0.f));
                    o.y = 0.5f * (fmaxf(acc1[mt][nt][1] + bb1y, 0.f) +
                                  fmaxf(acc2[mt][nt][1] + bb2y, 0.f));
                    *(float2*)(out + (size_t)r0 * 128 + col) = o;
                }
                if (r0 + 8 < n) {
                    float2 o;
                    o.x = 0.5f * (fmaxf(acc1[mt][nt][2] + bb1x, 0.f) +
                                  fmaxf(acc2[mt][nt][2] + bb2x, 0.f));
                    o.y = 0.5f * (fmaxf(acc1[mt][nt][3] + bb1y, 0.f) +
                                  fmaxf(acc2[mt][nt][3] + bb2y, 0.f));
                    *(float2*)(out + (size_t)(r0 + 8) * 128 + col) = o;
                }
            }
        }
    }
}

extern "C" void kernel_launch(void* const* d_in, const int* in_sizes, int n_in,
                              void* d_out, int out_size) {
    const float* x  = (const float*)d_in[0];
    const int*   ei = (const int*)d_in[1];
    const float* W1 = (const float*)d_in[2];
    const float* b1 = (const float*)d_in[3];
    const float* W2 = (const float*)d_in[4];
    const float* b2 = (const float*)d_in[5];
    float* out = (float*)d_out;

    int n_nodes = in_sizes[0] / DD;       // 50000
    int n_edges = in_sizes[1] / 2;        // 600000
    const int* src = ei;
    const int* dst = ei + n_edges;

    int nb_nodes = (n_nodes + 255) / 256;
    int nf4      = n_nodes * 32;          // float4 groups in x
    int nb_prep  = (nf4 + 255) / 256;     // covers both convert + scatter ranges

    k_prepscatter<<<nb_prep, 256>>>(x, nf4, src, dst, n_edges);
    k_dinv<<<nb_nodes, 256>>>(n_nodes);
    {
        int blocks = (n_nodes * 32 + 255) / 256;
        k_agg_gather<<<blocks, 256>>>(n_nodes);
    }
    {
        int smem_bytes = 3 * 128 * PH * 2;   // 104448
        cudaFuncSetAttribute(k_gemm,
                             cudaFuncAttributeMaxDynamicSharedMemorySize, smem_bytes);
        int ntiles = (n_nodes + BM - 1) / BM;
        k_gemm<<<GEMM_GRID, 512, smem_bytes>>>(W1, b1, W2, b2, out, n_nodes, ntiles);
    }
}

// round 14
// speedup vs baseline: 5.2323x; 1.0268x over previous
#include <cuda_runtime.h>
#include <cuda_fp16.h>
#include <string.h>

#define NN 50000
#define DD 128
#define CAP 128        // per-node bucket capacity; P(Poisson(12) > 128) ~ 1e-80

// bit-reinterpretation helpers
__device__ __forceinline__ unsigned h2_to_u(__half2 h) {
    unsigned u; memcpy(&u, &h, 4); return u;
}
__device__ __forceinline__ __half2 u_to_h2(unsigned u) {
    __half2 h; memcpy(&h, &u, 4); return h;
}
// packed fp32x2 helpers (Blackwell FFMA2 path)
__device__ __forceinline__ unsigned long long packf2(float lo, float hi) {
    unsigned long long r;
    asm("mov.b64 %0, {%1, %2};" : "=l"(r) : "f"(lo), "f"(hi));
    return r;
}
__device__ __forceinline__ void unpackf2(unsigned long long v, float& lo, float& hi) {
    asm("mov.b64 {%0, %1}, %2;" : "=f"(lo), "=f"(hi) : "l"(v));
}
__device__ __forceinline__ void ffma2p(unsigned long long& d,
                                       unsigned long long a, unsigned long long b) {
    asm("fma.rn.f32x2 %0, %1, %2, %0;" : "+l"(d) : "l"(a), "l"(b));
}

// scratch (static __device__ — zero-initialized at module load)
__device__ int   g_cnt[NN];                  // bucket cursors / degree (re-zeroed by k_dinv)
__device__ int   g_deg[NN];                  // degree snapshot for gather
__device__ float g_dinv[NN];                 // 1/sqrt(deg+1)
__device__ int   g_bucket[(size_t)NN * CAP]; // per-dst src lists (fixed stride)
__device__ __align__(16) __half g_xh[(size_t)NN * DD];   // x in fp16
__device__ __align__(16) __half g_yh[(size_t)NN * DD];   // y = A_hat @ x, fp16

// ---------------- prep + scatter fused ----------------
__global__ void k_prepscatter(const float* __restrict__ x, int nf4,
                              const int* __restrict__ src,
                              const int* __restrict__ dst, int e) {
    int i = blockIdx.x * blockDim.x + threadIdx.x;
    if (i < nf4) {
        float4 v = ((const float4*)x)[i];
        uint2 h;
        h.x = h2_to_u(__floats2half2_rn(v.x, v.y));
        h.y = h2_to_u(__floats2half2_rn(v.z, v.w));
        ((uint2*)g_xh)[i] = h;
    }
    int i0 = i * 4;
    if (i0 + 4 <= e) {
        int4 s4 = *(const int4*)(src + i0);
        int4 d4 = *(const int4*)(dst + i0);
        int p0 = -1, p1 = -1, p2 = -1, p3 = -1;
        if ((unsigned)s4.x < NN && (unsigned)d4.x < NN) p0 = atomicAdd(&g_cnt[d4.x], 1);
        if ((unsigned)s4.y < NN && (unsigned)d4.y < NN) p1 = atomicAdd(&g_cnt[d4.y], 1);
        if ((unsigned)s4.z < NN && (unsigned)d4.z < NN) p2 = atomicAdd(&g_cnt[d4.z], 1);
        if ((unsigned)s4.w < NN && (unsigned)d4.w < NN) p3 = atomicAdd(&g_cnt[d4.w], 1);
        if (p0 >= 0 && p0 < CAP) g_bucket[(size_t)d4.x * CAP + p0] = s4.x;
        if (p1 >= 0 && p1 < CAP) g_bucket[(size_t)d4.y * CAP + p1] = s4.y;
        if (p2 >= 0 && p2 < CAP) g_bucket[(size_t)d4.z * CAP + p2] = s4.z;
        if (p3 >= 0 && p3 < CAP) g_bucket[(size_t)d4.w * CAP + p3] = s4.w;
    } else if (i0 < e) {
        for (int j = i0; j < e; j++) {
            unsigned s = (unsigned)src[j], d = (unsigned)dst[j];
            if (s < NN && d < NN) {
                int p = atomicAdd(&g_cnt[d], 1);
                if (p < CAP) g_bucket[(size_t)d * CAP + p] = (int)s;
            }
        }
    }
}

// ---------------- dinv + degree snapshot + cursor re-arm ----------------
__global__ void k_dinv(int n) {
    int i = blockIdx.x * blockDim.x + threadIdx.x;
    if (i < n) {
        int c = g_cnt[i];
        g_deg[i] = c < CAP ? c : CAP;
        g_dinv[i] = rsqrtf((float)c + 1.0f);   // +1 self loop
        g_cnt[i] = 0;                          // re-arm for next graph replay
    }
}

// ---------------- gather (fp16 x, packed fp32x2 accumulate, fp16 y out) ----------
__global__ void __launch_bounds__(256) k_agg_gather(int n) {
    __shared__ int   swidx[8 * 32];
    __shared__ float swnorm[8 * 32];
    int warp = (blockIdx.x * blockDim.x + threadIdx.x) >> 5;
    int wl   = (threadIdx.x >> 5) * 32;
    int lane = threadIdx.x & 31;
    if (warp >= n) return;
    int d = warp;

    float dd = g_dinv[d];
    float ss = dd * dd;
    uint2 sh = __ldg((const uint2*)g_xh + (size_t)d * 32 + lane);
    float2 sa = __half22float2(u_to_h2(sh.x));
    float2 sb = __half22float2(u_to_h2(sh.y));
    unsigned long long acc01 = packf2(sa.x * ss, sa.y * ss);
    unsigned long long acc23 = packf2(sb.x * ss, sb.y * ss);

    int deg = g_deg[d];
    const int* bkt = g_bucket + (size_t)d * CAP;
    int dq = deg < 32 ? deg : 32;

    if (lane < dq) {
        int s = __ldg(bkt + lane);
        swidx[wl + lane] = s;
        swnorm[wl + lane] = g_dinv[s] * dd;
    }
    __syncwarp();

    int e = 0;
    for (; e + 8 <= dq; e += 8) {
        uint2 v[8]; float nm[8];
        #pragma unroll
        for (int q = 0; q < 8; q++) {
            int s = swidx[wl + e + q];
            nm[q] = swnorm[wl + e + q];
            v[q] = __ldg((const uint2*)g_xh + (size_t)s * 32 + lane);
        }
        #pragma unroll
        for (int q = 0; q < 8; q++) {
            float2 a = __half22float2(u_to_h2(v[q].x));
            float2 b = __half22float2(u_to_h2(v[q].y));
            unsigned long long nm2 = packf2(nm[q], nm[q]);
            ffma2p(acc01, packf2(a.x, a.y), nm2);
            ffma2p(acc23, packf2(b.x, b.y), nm2);
        }
    }
    for (; e < dq; e++) {
        int s = swidx[wl + e];
        float nmv = swnorm[wl + e];
        uint2 v = __ldg((const uint2*)g_xh + (size_t)s * 32 + lane);
        float2 a = __half22float2(u_to_h2(v.x));
        float2 b = __half22float2(u_to_h2(v.y));
        unsigned long long nm2 = packf2(nmv, nmv);
        ffma2p(acc01, packf2(a.x, a.y), nm2);
        ffma2p(acc23, packf2(b.x, b.y), nm2);
    }
    for (int j = 32; j < deg; j++) {
        int s = __ldg(bkt + j);
        float nmv = g_dinv[s] * dd;
        uint2 v = __ldg((const uint2*)g_xh + (size_t)s * 32 + lane);
        float2 a = __half22float2(u_to_h2(v.x));
        float2 b = __half22float2(u_to_h2(v.y));
        unsigned long long nm2 = packf2(nmv, nmv);
        ffma2p(acc01, packf2(a.x, a.y), nm2);
        ffma2p(acc23, packf2(b.x, b.y), nm2);
    }
    float a0, a1, a2, a3;
    unpackf2(acc01, a0, a1);
    unpackf2(acc23, a2, a3);
    uint2 o;
    o.x = h2_to_u(__floats2half2_rn(a0, a1));
    o.y = h2_to_u(__floats2half2_rn(a2, a3));
    ((uint2*)g_yh)[(size_t)d * 32 + lane] = o;
}

// ---------------- persistent dual fp16 MMA GEMM: cp.async pipeline + ldmatrix ----
#define BM   128
#define PH   136        // half pitch: 272B row stride (17x16B), conflict-free LDSM
#define GEMM_GRID 148

__device__ __forceinline__ void mma_f16(float* c, const unsigned* a,
                                        unsigned b0, unsigned b1) {
    asm volatile(
        "mma.sync.aligned.m16n8k16.row.col.f32.f16.f16.f32 "
        "{%0,%1,%2,%3}, {%4,%5,%6,%7}, {%8,%9}, {%0,%1,%2,%3};"
        : "+f"(c[0]), "+f"(c[1]), "+f"(c[2]), "+f"(c[3])
        : "r"(a[0]), "r"(a[1]), "r"(a[2]), "r"(a[3]), "r"(b0), "r"(b1));
}

__device__ __forceinline__ void ldsm_x4(unsigned& r0, unsigned& r1,
                                        unsigned& r2, unsigned& r3, unsigned addr) {
    asm volatile("ldmatrix.sync.aligned.m8n8.x4.shared.b16 {%0,%1,%2,%3}, [%4];"
        : "=r"(r0), "=r"(r1), "=r"(r2), "=r"(r3) : "r"(addr));
}

__device__ __forceinline__ void cp_async16(unsigned d, const void* s, int src_bytes) {
    asm volatile("cp.async.cg.shared.global [%0], [%1], 16, %2;"
        :: "r"(d), "l"(s), "r"(src_bytes) : "memory");
}
__device__ __forceinline__ void cp_commit() {
    asm volatile("cp.async.commit_group;" ::: "memory");
}
__device__ __forceinline__ void cp_wait0() {
    asm volatile("cp.async.wait_group 0;" ::: "memory");
}

__global__ void __launch_bounds__(512, 1)
k_gemm(const float* __restrict__ W1, const float* __restrict__ b1,
       const float* __restrict__ W2, const float* __restrict__ b2,
       float* __restrict__ out, int n, int ntiles) {
    extern __shared__ __half smh[];
    __half* W1t = smh;                       // [n][k]: 128 x PH
    __half* W2t = smh + 128 * PH;            // 128 x PH
    __half* Ys0 = smh + 2 * 128 * PH;        // BM x PH (buffer 0)
    __half* Ys1 = Ys0 + BM * PH;             // BM x PH (buffer 1)

    int tid  = threadIdx.x;
    int lane = tid & 31;
    int wid  = tid >> 5;
    int wm = wid >> 2, wn = wid & 3;
    int g  = lane >> 2, tig = lane & 3;

    unsigned ysb[2];
    ysb[0] = (unsigned)__cvta_generic_to_shared(Ys0);
    ysb[1] = (unsigned)__cvta_generic_to_shared(Ys1);

    // stage weights once, TRANSPOSED to [n][k]
    for (int i = tid; i < 16384; i += 512) {
        int row = i >> 7, col = i & 127;    // W[k=row][n=col]
        W1t[col * PH + row] = __float2half(__ldg(W1 + i));
        W2t[col * PH + row] = __float2half(__ldg(W2 + i));
    }

    // ldmatrix per-lane address offsets (bytes)
    // A (x4): lanes 0-7 rows r..r+7 @k0 | 8-15 rows r+8.. @k0 | 16-23 r.. @k0+8 | 24-31 r+8.. @k0+8
    unsigned aOff[2];
    #pragma unroll
    for (int mt = 0; mt < 2; mt++) {
        int row = wm * 32 + mt * 16 + (lane & 15);
        int koff = (lane >> 4) ? 8 : 0;
        aOff[mt] = (unsigned)((row * PH + koff) * 2);
    }
    // B (x4): mat0/1 = W1 (k0, k0+8), mat2/3 = W2 (k0, k0+8); one per nt
    unsigned bAddr[4];
    #pragma unroll
    for (int nt = 0; nt < 4; nt++) {
        int nrow = wn * 32 + nt * 8 + (lane & 7);
        int koff = ((lane >> 3) & 1) ? 8 : 0;
        const __half* base = (lane < 16) ? W1t : W2t;
        bAddr[nt] = (unsigned)__cvta_generic_to_shared(base) +
                    (unsigned)((nrow * PH + koff) * 2);
    }

    // stage Ys tile into buffer via cp.async (16B chunks, OOB zero-filled)
    auto stage = [&](int tile, int buf) {
        int m0 = tile * BM;
        #pragma unroll
        for (int i = tid; i < BM * 16; i += 512) {
            int row = i >> 4, c16 = i & 15;
            int gg = m0 + row;
            unsigned dstd = ysb[buf] + (unsigned)((row * PH + c16 * 8) * 2);
            const void* srcp = (const void*)((const uint4*)g_yh + (size_t)(gg < n ? gg : 0) * 16 + c16);
            cp_async16(dstd, srcp, gg < n ? 16 : 0);
        }
        cp_commit();
    };

    int buf = 0;
    int t0 = blockIdx.x;
    if (t0 < ntiles) stage(t0, 0);

    for (int tile = t0; tile < ntiles; tile += GEMM_GRID) {
        int nxt = tile + GEMM_GRID;
        cp_wait0();
        __syncthreads();                 // staged buf visible to all warps
        if (nxt < ntiles) stage(nxt, buf ^ 1);

        float acc1[2][4][4];
        float acc2[2][4][4];
        #pragma unroll
        for (int mt = 0; mt < 2; mt++)
            #pragma unroll
            for (int nt = 0; nt < 4; nt++)
                #pragma unroll
                for (int q = 0; q < 4; q++) { acc1[mt][nt][q] = 0.f; acc2[mt][nt][q] = 0.f; }

        unsigned yb = ysb[buf];
        #pragma unroll
        for (int ks = 0; ks < 8; ks++) {
            unsigned kb = ks * 32;       // 16 halves = 32 bytes
            unsigned a[2][4];
            ldsm_x4(a[0][0], a[0][1], a[0][2], a[0][3], yb + aOff[0] + kb);
            ldsm_x4(a[1][0], a[1][1], a[1][2], a[1][3], yb + aOff[1] + kb);
            #pragma unroll
            for (int nt = 0; nt < 4; nt++) {
                unsigned w1b0, w1b1, w2b0, w2b1;
                ldsm_x4(w1b0, w1b1, w2b0, w2b1, bAddr[nt] + kb);
                mma_f16(acc1[0][nt], a[0], w1b0, w1b1);
                mma_f16(acc1[1][nt], a[1], w1b0, w1b1);
                mma_f16(acc2[0][nt], a[0], w2b0, w2b1);
                mma_f16(acc2[1][nt], a[1], w2b0, w2b1);
            }
        }

        int m0 = tile * BM;
        #pragma unroll
        for (int mt = 0; mt < 2; mt++) {
            int r0 = m0 + wm * 32 + mt * 16 + g;
            #pragma unroll
            for (int nt = 0; nt < 4; nt++) {
                int col = wn * 32 + nt * 8 + 2 * tig;
                float bb1x = __ldg(b1 + col), bb1y = __ldg(b1 + col + 1);
                float bb2x = __ldg(b2 + col), bb2y = __ldg(b2 + col + 1);
                if (r0 < n) {
                    float2 o;
                    o.x = 0.5f * (fmaxf(acc1[mt][nt][0] + bb1x, 0.f) +
                                  fmaxf(acc2[mt][nt][0] + bb2x, 0.f));
                    o.y = 0.5f * (fmaxf(acc1[mt][nt][1] + bb1y, 0.f) +
                                  fmaxf(acc2[mt][nt][1] + bb2y, 0.f));
                    *(float2*)(out + (size_t)r0 * 128 + col) = o;
                }
                if (r0 + 8 < n) {
                    float2 o;
                    o.x = 0.5f * (fmaxf(acc1[mt][nt][2] + bb1x, 0.f) +
                                  fmaxf(acc2[mt][nt][2] + bb2x, 0.f));
                    o.y = 0.5f * (fmaxf(acc1[mt][nt][3] + bb1y, 0.f) +
                                  fmaxf(acc2[mt][nt][3] + bb2y, 0.f));
                    *(float2*)(out + (size_t)(r0 + 8) * 128 + col) = o;
                }
            }
        }
        __syncthreads();                 // all reads of buf done before it is restaged
        buf ^= 1;
    }
}

extern "C" void kernel_launch(void* const* d_in, const int* in_sizes, int n_in,
                              void* d_out, int out_size) {
    const float* x  = (const float*)d_in[0];
    const int*   ei = (const int*)d_in[1];
    const float* W1 = (const float*)d_in[2];
    const float* b1 = (const float*)d_in[3];
    const float* W2 = (const float*)d_in[4];
    const float* b2 = (const float*)d_in[5];
    float* out = (float*)d_out;

    int n_nodes = in_sizes[0] / DD;       // 50000
    int n_edges = in_sizes[1] / 2;        // 600000
    const int* src = ei;
    const int* dst = ei + n_edges;

    int nb_nodes = (n_nodes + 255) / 256;
    int nf4      = n_nodes * 32;          // float4 groups in x
    int nb_prep  = (nf4 + 255) / 256;     // covers both convert + scatter ranges

    k_prepscatter<<<nb_prep, 256>>>(x, nf4, src, dst, n_edges);
    k_dinv<<<nb_nodes, 256>>>(n_nodes);
    {
        int blocks = (n_nodes * 32 + 255) / 256;
        k_agg_gather<<<blocks, 256>>>(n_nodes);
    }
    {
        int smem_bytes = (2 * 128 * PH + 2 * BM * PH) * 2;   // 139264
        cudaFuncSetAttribute(k_gemm,
                             cudaFuncAttributeMaxDynamicSharedMemorySize, smem_bytes);
        int ntiles = (n_nodes + BM - 1) / BM;
        k_gemm<<<GEMM_GRID, 512, smem_bytes>>>(W1, b1, W2, b2, out, n_nodes, ntiles);
    }
}